// round 3
// baseline (speedup 1.0000x reference)
#include <cuda_runtime.h>

#define DFEAT 128
#define NMAX  50000
#define EMAX  800000
#define BN_EPS 1e-5f
#define SCAN_BLK 256

// -------- scratch (static device globals: no allocation) --------
// float4 element type guarantees 16B alignment for vector ld/st.
__device__ float4 g_h[NMAX * 32];         // h = x @ W
__device__ float4 g_acc[NMAX * 32];       // gathered output (pre-BN)
__device__ float  g_dinv[NMAX];
__device__ int    g_ideg[NMAX];           // in-degree (edges only)
__device__ int    g_indptr[NMAX];         // CSR start offsets
__device__ int    g_cursor[NMAX];         // fill cursors
__device__ int    g_srcs[EMAX];           // CSR-ordered edge source node ids
__device__ int    g_bsum[SCAN_BLK];       // block sums for scan
__device__ __align__(16) float g_sum[DFEAT];
__device__ __align__(16) float g_sumsq[DFEAT];

// -------- 1. init --------
__global__ void init_kernel(int N) {
    int i = blockIdx.x * blockDim.x + threadIdx.x;
    if (i < N) g_ideg[i] = 0;
    if (i < DFEAT) { g_sum[i] = 0.0f; g_sumsq[i] = 0.0f; }
}

// -------- 2. in-degree count (edge_index is int32: [src row | dst row]) ----
__global__ void degree_kernel(const int* __restrict__ ei, int E, int N) {
    int e = blockIdx.x * blockDim.x + threadIdx.x;
    if (e < E) {
        int col = ei[E + e];                // target
        if ((unsigned)col < (unsigned)N) atomicAdd(&g_ideg[col], 1);
    }
}

// -------- 3a. per-block degree sums --------
__global__ void scan_blocksum_kernel(int N) {
    __shared__ int s[SCAN_BLK];
    int i = blockIdx.x * SCAN_BLK + threadIdx.x;
    s[threadIdx.x] = (i < N) ? g_ideg[i] : 0;
    __syncthreads();
    for (int off = SCAN_BLK / 2; off > 0; off >>= 1) {
        if (threadIdx.x < off) s[threadIdx.x] += s[threadIdx.x + off];
        __syncthreads();
    }
    if (threadIdx.x == 0) g_bsum[blockIdx.x] = s[0];
}

// -------- 3b. single-block exclusive scan of block sums --------
__global__ void scan_top_kernel(int NB) {
    __shared__ int s[SCAN_BLK];
    int t = threadIdx.x;
    int v = (t < NB) ? g_bsum[t] : 0;
    s[t] = v;
    __syncthreads();
    for (int off = 1; off < SCAN_BLK; off <<= 1) {
        int add = (t >= off) ? s[t - off] : 0;
        __syncthreads();
        s[t] += add;
        __syncthreads();
    }
    if (t < NB) g_bsum[t] = s[t] - v;   // exclusive
}

// -------- 3c. per-block exclusive scan -> indptr, cursor, dinv --------
__global__ void scan_final_kernel(int N) {
    __shared__ int s[SCAN_BLK];
    int i = blockIdx.x * SCAN_BLK + threadIdx.x;
    int t = threadIdx.x;
    int v = (i < N) ? g_ideg[i] : 0;
    s[t] = v;
    __syncthreads();
    for (int off = 1; off < SCAN_BLK; off <<= 1) {
        int add = (t >= off) ? s[t - off] : 0;
        __syncthreads();
        s[t] += add;
        __syncthreads();
    }
    if (i < N) {
        int start = g_bsum[blockIdx.x] + s[t] - v;
        g_indptr[i] = start;
        g_cursor[i] = start;
        g_dinv[i] = rsqrtf((float)(v + 1));   // +1 self loop
    }
}

// -------- 4. CSR fill: bucket edge sources by target --------
__global__ void fill_kernel(const int* __restrict__ ei, int E, int N) {
    int e = blockIdx.x * blockDim.x + threadIdx.x;
    if (e < E) {
        int row = ei[e];
        int col = ei[E + e];
        if ((unsigned)row < (unsigned)N && (unsigned)col < (unsigned)N) {
            int pos = atomicAdd(&g_cursor[col], 1);
            if ((unsigned)pos < (unsigned)EMAX) g_srcs[pos] = row;
        }
    }
}

// -------- 5. GEMM h = x @ W --------
// block (32,8): lane tx owns cols [4tx,4tx+3], ty owns 8 rows.
// W (64KB) lives in L1; x rows are warp-broadcast LDG.128.
__global__ void __launch_bounds__(256) gemm_kernel(
        const float* __restrict__ x, const float* __restrict__ W, int N) {
    int tx = threadIdx.x;
    int ty = threadIdx.y;
    int row0 = blockIdx.x * 64 + ty * 8;

    const float4* W4 = (const float4*)W;
    const float4* x4 = (const float4*)x;

    float4 acc[8];
#pragma unroll
    for (int r = 0; r < 8; r++) acc[r] = make_float4(0.f, 0.f, 0.f, 0.f);

#pragma unroll 4
    for (int k4 = 0; k4 < 32; k4++) {
        float4 w0 = W4[(k4 * 4 + 0) * 32 + tx];
        float4 w1 = W4[(k4 * 4 + 1) * 32 + tx];
        float4 w2 = W4[(k4 * 4 + 2) * 32 + tx];
        float4 w3 = W4[(k4 * 4 + 3) * 32 + tx];
#pragma unroll
        for (int r = 0; r < 8; r++) {
            int gr = row0 + r;
            float4 xv = (gr < N) ? x4[gr * 32 + k4] : make_float4(0.f, 0.f, 0.f, 0.f);
            acc[r].x = fmaf(xv.x, w0.x, acc[r].x);
            acc[r].y = fmaf(xv.x, w0.y, acc[r].y);
            acc[r].z = fmaf(xv.x, w0.z, acc[r].z);
            acc[r].w = fmaf(xv.x, w0.w, acc[r].w);
            acc[r].x = fmaf(xv.y, w1.x, acc[r].x);
            acc[r].y = fmaf(xv.y, w1.y, acc[r].y);
            acc[r].z = fmaf(xv.y, w1.z, acc[r].z);
            acc[r].w = fmaf(xv.y, w1.w, acc[r].w);
            acc[r].x = fmaf(xv.z, w2.x, acc[r].x);
            acc[r].y = fmaf(xv.z, w2.y, acc[r].y);
            acc[r].z = fmaf(xv.z, w2.z, acc[r].z);
            acc[r].w = fmaf(xv.z, w2.w, acc[r].w);
            acc[r].x = fmaf(xv.w, w3.x, acc[r].x);
            acc[r].y = fmaf(xv.w, w3.y, acc[r].y);
            acc[r].z = fmaf(xv.w, w3.z, acc[r].z);
            acc[r].w = fmaf(xv.w, w3.w, acc[r].w);
        }
    }

#pragma unroll
    for (int r = 0; r < 8; r++) {
        int gr = row0 + r;
        if (gr < N) g_h[gr * 32 + tx] = acc[r];
    }
}

// -------- 6. gather: one warp per destination node, no float atomics ----
__global__ void __launch_bounds__(256) gather_kernel(
        const float* __restrict__ b, int N) {
    int w = (blockIdx.x * blockDim.x + threadIdx.x) >> 5;
    int lane = threadIdx.x & 31;
    if (w >= N) return;

    float di = g_dinv[w];
    int start = g_indptr[w];
    int cnt = g_ideg[w];

    // self loop + bias
    float4 a = g_h[w * 32 + lane];
    float selfn = di * di;
    float4 bb = ((const float4*)b)[lane];
    a.x = fmaf(a.x, selfn, bb.x);
    a.y = fmaf(a.y, selfn, bb.y);
    a.z = fmaf(a.z, selfn, bb.z);
    a.w = fmaf(a.w, selfn, bb.w);

    for (int j = 0; j < cnt; j++) {
        int row = g_srcs[start + j];          // warp-broadcast load
        float nrm = di * g_dinv[row];
        float4 v = g_h[row * 32 + lane];
        a.x = fmaf(v.x, nrm, a.x);
        a.y = fmaf(v.y, nrm, a.y);
        a.z = fmaf(v.z, nrm, a.z);
        a.w = fmaf(v.w, nrm, a.w);
    }

    g_acc[w * 32 + lane] = a;
}

// -------- 7. BN column stats --------
__global__ void bnstats_kernel(int N) {
    int d = threadIdx.x;   // 128 threads = 128 columns
    const float* accf = (const float*)g_acc;
    float s = 0.f, s2 = 0.f;
    for (int r = blockIdx.x; r < N; r += gridDim.x) {
        float v = accf[r * DFEAT + d];
        s += v;
        s2 += v * v;
    }
    atomicAdd(&g_sum[d], s);
    atomicAdd(&g_sumsq[d], s2);
}

// -------- 8. BN normalize + relu + residual --------
__global__ void finalize_kernel(const float* __restrict__ x,
                                const float* __restrict__ gamma,
                                const float* __restrict__ beta,
                                float* __restrict__ out, int N) {
    int i = blockIdx.x * blockDim.x + threadIdx.x;
    int total = N * 32;       // float4 units
    if (i >= total) return;
    int d4 = i & 31;
    float inv_n = 1.0f / (float)N;

    float4 a  = g_acc[i];
    float4 xv = ((const float4*)x)[i];
    float4 g  = ((const float4*)gamma)[d4];
    float4 bt = ((const float4*)beta)[d4];
    float4 sm = ((const float4*)g_sum)[d4];
    float4 sq = ((const float4*)g_sumsq)[d4];

    float4 o;
    {
        float m = sm.x * inv_n;
        float var = sq.x * inv_n - m * m;
        float v = (a.x - m) * rsqrtf(var + BN_EPS) * g.x + bt.x;
        o.x = fmaxf(v, 0.f) + xv.x;
    }
    {
        float m = sm.y * inv_n;
        float var = sq.y * inv_n - m * m;
        float v = (a.y - m) * rsqrtf(var + BN_EPS) * g.y + bt.y;
        o.y = fmaxf(v, 0.f) + xv.y;
    }
    {
        float m = sm.z * inv_n;
        float var = sq.z * inv_n - m * m;
        float v = (a.z - m) * rsqrtf(var + BN_EPS) * g.z + bt.z;
        o.z = fmaxf(v, 0.f) + xv.z;
    }
    {
        float m = sm.w * inv_n;
        float var = sq.w * inv_n - m * m;
        float v = (a.w - m) * rsqrtf(var + BN_EPS) * g.w + bt.w;
        o.w = fmaxf(v, 0.f) + xv.w;
    }
    ((float4*)out)[i] = o;
}

extern "C" void kernel_launch(void* const* d_in, const int* in_sizes, int n_in,
                              void* d_out, int out_size) {
    const float* x     = (const float*)d_in[0];
    const int*   ei    = (const int*)d_in[1];    // int32 per harness dtype set
    const float* W     = (const float*)d_in[2];
    const float* b     = (const float*)d_in[3];
    const float* gamma = (const float*)d_in[4];
    const float* beta  = (const float*)d_in[5];
    float*       out   = (float*)d_out;

    int N = in_sizes[0] / DFEAT;
    int E = in_sizes[1] / 2;
    if (E > EMAX) E = EMAX;
    int NB = (N + SCAN_BLK - 1) / SCAN_BLK;   // 196 for N=50000 (<= 256)

    init_kernel<<<(N + 255) / 256, 256>>>(N);
    degree_kernel<<<(E + 255) / 256, 256>>>(ei, E, N);

    scan_blocksum_kernel<<<NB, SCAN_BLK>>>(N);
    scan_top_kernel<<<1, SCAN_BLK>>>(NB);
    scan_final_kernel<<<NB, SCAN_BLK>>>(N);

    fill_kernel<<<(E + 255) / 256, 256>>>(ei, E, N);

    dim3 gblk(32, 8);
    gemm_kernel<<<(N + 63) / 64, gblk>>>(x, W, N);

    gather_kernel<<<(N * 32 + 255) / 256, 256>>>(b, N);

    bnstats_kernel<<<512, 128>>>(N);
    finalize_kernel<<<(N * 32 + 255) / 256, 256>>>(x, gamma, beta, out, N);
}

// round 4
// speedup vs baseline: 1.0328x; 1.0328x over previous
#include <cuda_runtime.h>

#define DFEAT 128
#define NMAX  50000
#define EMAX  800000
#define BN_EPS 1e-5f
#define SCAN_BLK 256

// -------- scratch (static device globals: no allocation) --------
__device__ float4 g_h[NMAX * 32];         // h = x @ W
__device__ float4 g_acc[NMAX * 32];       // gathered output (pre-BN)
__device__ float  g_dinv[NMAX];
__device__ int    g_ideg[NMAX];           // in-degree (edges only)
__device__ int    g_indptr[NMAX];         // CSR start offsets
__device__ int    g_cursor[NMAX];         // fill cursors
__device__ int    g_srcs[EMAX];           // CSR-ordered edge source ids
__device__ int    g_bsum[SCAN_BLK];       // block sums for scan
__device__ __align__(16) float g_sum[DFEAT];
__device__ __align__(16) float g_sumsq[DFEAT];

// -------- 0. init --------
__global__ void init_kernel(int N) {
    int i = blockIdx.x * blockDim.x + threadIdx.x;
    if (i < N) g_ideg[i] = 0;
    if (i < DFEAT) { g_sum[i] = 0.0f; g_sumsq[i] = 0.0f; }
}

// -------- 1. in-degree count --------
__global__ void degree_kernel(const int* __restrict__ ei, int E, int N) {
    int e = blockIdx.x * blockDim.x + threadIdx.x;
    if (e < E) {
        int col = ei[E + e];                // target
        if ((unsigned)col < (unsigned)N) atomicAdd(&g_ideg[col], 1);
    }
}

// -------- 2. per-block degree sums --------
__global__ void scan_blocksum_kernel(int N) {
    __shared__ int s[SCAN_BLK];
    int i = blockIdx.x * SCAN_BLK + threadIdx.x;
    s[threadIdx.x] = (i < N) ? g_ideg[i] : 0;
    __syncthreads();
    for (int off = SCAN_BLK / 2; off > 0; off >>= 1) {
        if (threadIdx.x < off) s[threadIdx.x] += s[threadIdx.x + off];
        __syncthreads();
    }
    if (threadIdx.x == 0) g_bsum[blockIdx.x] = s[0];
}

// -------- 3. single-block exclusive scan of block sums --------
__global__ void scan_top_kernel(int NB) {
    __shared__ int s[SCAN_BLK];
    int t = threadIdx.x;
    int v = (t < NB) ? g_bsum[t] : 0;
    s[t] = v;
    __syncthreads();
    for (int off = 1; off < SCAN_BLK; off <<= 1) {
        int add = (t >= off) ? s[t - off] : 0;
        __syncthreads();
        s[t] += add;
        __syncthreads();
    }
    if (t < NB) g_bsum[t] = s[t] - v;   // exclusive
}

// -------- 4. per-block exclusive scan -> indptr, cursor, dinv --------
__global__ void scan_final_kernel(int N) {
    __shared__ int s[SCAN_BLK];
    int i = blockIdx.x * SCAN_BLK + threadIdx.x;
    int t = threadIdx.x;
    int v = (i < N) ? g_ideg[i] : 0;
    s[t] = v;
    __syncthreads();
    for (int off = 1; off < SCAN_BLK; off <<= 1) {
        int add = (t >= off) ? s[t - off] : 0;
        __syncthreads();
        s[t] += add;
        __syncthreads();
    }
    if (i < N) {
        int start = g_bsum[blockIdx.x] + s[t] - v;
        g_indptr[i] = start;
        g_cursor[i] = start;
        g_dinv[i] = rsqrtf((float)(v + 1));   // +1 self loop
    }
}

// -------- 5. GEMM h = x @ W  (launch index 5 -> ncu -s5 captures it) ----
__global__ void __launch_bounds__(256) gemm_kernel(
        const float* __restrict__ x, const float* __restrict__ W, int N) {
    int tx = threadIdx.x;
    int ty = threadIdx.y;
    int row0 = blockIdx.x * 64 + ty * 8;

    const float4* W4 = (const float4*)W;
    const float4* x4 = (const float4*)x;

    float4 acc[8];
#pragma unroll
    for (int r = 0; r < 8; r++) acc[r] = make_float4(0.f, 0.f, 0.f, 0.f);

#pragma unroll 4
    for (int k4 = 0; k4 < 32; k4++) {
        float4 w0 = W4[(k4 * 4 + 0) * 32 + tx];
        float4 w1 = W4[(k4 * 4 + 1) * 32 + tx];
        float4 w2 = W4[(k4 * 4 + 2) * 32 + tx];
        float4 w3 = W4[(k4 * 4 + 3) * 32 + tx];
#pragma unroll
        for (int r = 0; r < 8; r++) {
            int gr = row0 + r;
            float4 xv = (gr < N) ? x4[gr * 32 + k4] : make_float4(0.f, 0.f, 0.f, 0.f);
            acc[r].x = fmaf(xv.x, w0.x, acc[r].x);
            acc[r].y = fmaf(xv.x, w0.y, acc[r].y);
            acc[r].z = fmaf(xv.x, w0.z, acc[r].z);
            acc[r].w = fmaf(xv.x, w0.w, acc[r].w);
            acc[r].x = fmaf(xv.y, w1.x, acc[r].x);
            acc[r].y = fmaf(xv.y, w1.y, acc[r].y);
            acc[r].z = fmaf(xv.y, w1.z, acc[r].z);
            acc[r].w = fmaf(xv.y, w1.w, acc[r].w);
            acc[r].x = fmaf(xv.z, w2.x, acc[r].x);
            acc[r].y = fmaf(xv.z, w2.y, acc[r].y);
            acc[r].z = fmaf(xv.z, w2.z, acc[r].z);
            acc[r].w = fmaf(xv.z, w2.w, acc[r].w);
            acc[r].x = fmaf(xv.w, w3.x, acc[r].x);
            acc[r].y = fmaf(xv.w, w3.y, acc[r].y);
            acc[r].z = fmaf(xv.w, w3.z, acc[r].z);
            acc[r].w = fmaf(xv.w, w3.w, acc[r].w);
        }
    }

#pragma unroll
    for (int r = 0; r < 8; r++) {
        int gr = row0 + r;
        if (gr < N) g_h[gr * 32 + tx] = acc[r];
    }
}

// -------- 6. CSR fill --------
__global__ void fill_kernel(const int* __restrict__ ei, int E, int N) {
    int e = blockIdx.x * blockDim.x + threadIdx.x;
    if (e < E) {
        int row = ei[e];
        int col = ei[E + e];
        if ((unsigned)row < (unsigned)N && (unsigned)col < (unsigned)N) {
            int pos = atomicAdd(&g_cursor[col], 1);
            if ((unsigned)pos < (unsigned)EMAX) g_srcs[pos] = row;
        }
    }
}

// -------- 7. gather (grid-stride warps, unroll-4) + fused BN stats ----
#define GATHER_BLOCKS 1184
__global__ void __launch_bounds__(256) gather_kernel(
        const float* __restrict__ b, int N) {
    __shared__ float s_sum[DFEAT];
    __shared__ float s_sumsq[DFEAT];
    int tid = threadIdx.x;
    if (tid < DFEAT) { s_sum[tid] = 0.f; s_sumsq[tid] = 0.f; }
    __syncthreads();

    int lane = tid & 31;
    int warp_g = (blockIdx.x * blockDim.x + tid) >> 5;
    int nwarps = (GATHER_BLOCKS * 256) >> 5;

    float4 bb = ((const float4*)b)[lane];

    // per-thread BN partials (4 feature columns: lane*4 .. lane*4+3)
    float ps0 = 0.f, ps1 = 0.f, ps2 = 0.f, ps3 = 0.f;
    float q0 = 0.f, q1 = 0.f, q2 = 0.f, q3 = 0.f;

    for (int w = warp_g; w < N; w += nwarps) {
        float di = g_dinv[w];
        int start = g_indptr[w];
        int cnt = g_ideg[w];

        // self loop + bias
        float4 a = g_h[w * 32 + lane];
        float selfn = di * di;
        a.x = fmaf(a.x, selfn, bb.x);
        a.y = fmaf(a.y, selfn, bb.y);
        a.z = fmaf(a.z, selfn, bb.z);
        a.w = fmaf(a.w, selfn, bb.w);

        int j = 0;
        for (; j + 4 <= cnt; j += 4) {
            int r0 = g_srcs[start + j + 0];
            int r1 = g_srcs[start + j + 1];
            int r2 = g_srcs[start + j + 2];
            int r3 = g_srcs[start + j + 3];
            float n0 = di * g_dinv[r0];
            float n1 = di * g_dinv[r1];
            float n2 = di * g_dinv[r2];
            float n3 = di * g_dinv[r3];
            float4 v0 = g_h[r0 * 32 + lane];
            float4 v1 = g_h[r1 * 32 + lane];
            float4 v2 = g_h[r2 * 32 + lane];
            float4 v3 = g_h[r3 * 32 + lane];
            a.x = fmaf(v0.x, n0, a.x); a.y = fmaf(v0.y, n0, a.y);
            a.z = fmaf(v0.z, n0, a.z); a.w = fmaf(v0.w, n0, a.w);
            a.x = fmaf(v1.x, n1, a.x); a.y = fmaf(v1.y, n1, a.y);
            a.z = fmaf(v1.z, n1, a.z); a.w = fmaf(v1.w, n1, a.w);
            a.x = fmaf(v2.x, n2, a.x); a.y = fmaf(v2.y, n2, a.y);
            a.z = fmaf(v2.z, n2, a.z); a.w = fmaf(v2.w, n2, a.w);
            a.x = fmaf(v3.x, n3, a.x); a.y = fmaf(v3.y, n3, a.y);
            a.z = fmaf(v3.z, n3, a.z); a.w = fmaf(v3.w, n3, a.w);
        }
        for (; j < cnt; j++) {
            int r = g_srcs[start + j];
            float nm = di * g_dinv[r];
            float4 v = g_h[r * 32 + lane];
            a.x = fmaf(v.x, nm, a.x); a.y = fmaf(v.y, nm, a.y);
            a.z = fmaf(v.z, nm, a.z); a.w = fmaf(v.w, nm, a.w);
        }

        g_acc[w * 32 + lane] = a;

        ps0 += a.x; ps1 += a.y; ps2 += a.z; ps3 += a.w;
        q0 = fmaf(a.x, a.x, q0); q1 = fmaf(a.y, a.y, q1);
        q2 = fmaf(a.z, a.z, q2); q3 = fmaf(a.w, a.w, q3);
    }

    // block-level BN partial reduction (8 warps share column mapping)
    int c = lane * 4;
    atomicAdd(&s_sum[c + 0], ps0);
    atomicAdd(&s_sum[c + 1], ps1);
    atomicAdd(&s_sum[c + 2], ps2);
    atomicAdd(&s_sum[c + 3], ps3);
    atomicAdd(&s_sumsq[c + 0], q0);
    atomicAdd(&s_sumsq[c + 1], q1);
    atomicAdd(&s_sumsq[c + 2], q2);
    atomicAdd(&s_sumsq[c + 3], q3);
    __syncthreads();

    if (tid < DFEAT) {
        atomicAdd(&g_sum[tid], s_sum[tid]);
        atomicAdd(&g_sumsq[tid], s_sumsq[tid]);
    }
}

// -------- 8. BN normalize + relu + residual --------
__global__ void finalize_kernel(const float* __restrict__ x,
                                const float* __restrict__ gamma,
                                const float* __restrict__ beta,
                                float* __restrict__ out, int N) {
    int i = blockIdx.x * blockDim.x + threadIdx.x;
    int total = N * 32;       // float4 units
    if (i >= total) return;
    int d4 = i & 31;
    float inv_n = 1.0f / (float)N;

    float4 a  = g_acc[i];
    float4 xv = ((const float4*)x)[i];
    float4 g  = ((const float4*)gamma)[d4];
    float4 bt = ((const float4*)beta)[d4];
    float4 sm = ((const float4*)g_sum)[d4];
    float4 sq = ((const float4*)g_sumsq)[d4];

    float4 o;
    {
        float m = sm.x * inv_n;
        float var = sq.x * inv_n - m * m;
        float v = (a.x - m) * rsqrtf(var + BN_EPS) * g.x + bt.x;
        o.x = fmaxf(v, 0.f) + xv.x;
    }
    {
        float m = sm.y * inv_n;
        float var = sq.y * inv_n - m * m;
        float v = (a.y - m) * rsqrtf(var + BN_EPS) * g.y + bt.y;
        o.y = fmaxf(v, 0.f) + xv.y;
    }
    {
        float m = sm.z * inv_n;
        float var = sq.z * inv_n - m * m;
        float v = (a.z - m) * rsqrtf(var + BN_EPS) * g.z + bt.z;
        o.z = fmaxf(v, 0.f) + xv.z;
    }
    {
        float m = sm.w * inv_n;
        float var = sq.w * inv_n - m * m;
        float v = (a.w - m) * rsqrtf(var + BN_EPS) * g.w + bt.w;
        o.w = fmaxf(v, 0.f) + xv.w;
    }
    ((float4*)out)[i] = o;
}

extern "C" void kernel_launch(void* const* d_in, const int* in_sizes, int n_in,
                              void* d_out, int out_size) {
    const float* x     = (const float*)d_in[0];
    const int*   ei    = (const int*)d_in[1];    // int32 per harness dtype set
    const float* W     = (const float*)d_in[2];
    const float* b     = (const float*)d_in[3];
    const float* gamma = (const float*)d_in[4];
    const float* beta  = (const float*)d_in[5];
    float*       out   = (float*)d_out;

    int N = in_sizes[0] / DFEAT;
    int E = in_sizes[1] / 2;
    if (E > EMAX) E = EMAX;
    int NB = (N + SCAN_BLK - 1) / SCAN_BLK;   // 196 for N=50000 (<= 256)

    init_kernel<<<(N + 255) / 256, 256>>>(N);                 // 0
    degree_kernel<<<(E + 255) / 256, 256>>>(ei, E, N);        // 1
    scan_blocksum_kernel<<<NB, SCAN_BLK>>>(N);                // 2
    scan_top_kernel<<<1, SCAN_BLK>>>(NB);                     // 3
    scan_final_kernel<<<NB, SCAN_BLK>>>(N);                   // 4

    dim3 gblk(32, 8);
    gemm_kernel<<<(N + 63) / 64, gblk>>>(x, W, N);            // 5 <- ncu -s5

    fill_kernel<<<(E + 255) / 256, 256>>>(ei, E, N);          // 6
    gather_kernel<<<GATHER_BLOCKS, 256>>>(b, N);              // 7
    finalize_kernel<<<(N * 32 + 255) / 256, 256>>>(x, gamma, beta, out, N); // 8
}

// round 5
// speedup vs baseline: 1.0793x; 1.0450x over previous
#include <cuda_runtime.h>

#define DFEAT 128
#define NMAX  50000
#define EMAX  800000
#define BN_EPS 1e-5f
#define SCAN_BLK 256

// -------- scratch (static device globals: no allocation) --------
__device__ float4 g_h[NMAX * 32];         // h = x @ W
__device__ float4 g_acc[NMAX * 32];       // gathered output (pre-BN)
__device__ float  g_dinv[NMAX];
__device__ int    g_ideg[NMAX];           // in-degree (edges only)
__device__ int    g_indptr[NMAX];         // CSR start offsets
__device__ int    g_cursor[NMAX];         // fill cursors
__device__ int    g_srcs[EMAX];           // CSR-ordered edge source ids
__device__ int    g_bsum[SCAN_BLK];       // block sums for scan
__device__ __align__(16) float g_sum[DFEAT];
__device__ __align__(16) float g_sumsq[DFEAT];

// -------- 0. init --------
__global__ void init_kernel(int N) {
    int i = blockIdx.x * blockDim.x + threadIdx.x;
    if (i < N) g_ideg[i] = 0;
    if (i < DFEAT) { g_sum[i] = 0.0f; g_sumsq[i] = 0.0f; }
}

// -------- 1. in-degree count --------
__global__ void degree_kernel(const int* __restrict__ ei, int E, int N) {
    int e = blockIdx.x * blockDim.x + threadIdx.x;
    if (e < E) {
        int col = ei[E + e];                // target
        if ((unsigned)col < (unsigned)N) atomicAdd(&g_ideg[col], 1);
    }
}

// -------- 2. per-block degree sums --------
__global__ void scan_blocksum_kernel(int N) {
    __shared__ int s[SCAN_BLK];
    int i = blockIdx.x * SCAN_BLK + threadIdx.x;
    s[threadIdx.x] = (i < N) ? g_ideg[i] : 0;
    __syncthreads();
    for (int off = SCAN_BLK / 2; off > 0; off >>= 1) {
        if (threadIdx.x < off) s[threadIdx.x] += s[threadIdx.x + off];
        __syncthreads();
    }
    if (threadIdx.x == 0) g_bsum[blockIdx.x] = s[0];
}

// -------- GEMM h = x @ W  (4th launch -> ncu capture slot) --------
__global__ void __launch_bounds__(256) gemm_kernel(
        const float* __restrict__ x, const float* __restrict__ W, int N) {
    int tx = threadIdx.x;
    int ty = threadIdx.y;
    int row0 = blockIdx.x * 64 + ty * 8;

    const float4* W4 = (const float4*)W;
    const float4* x4 = (const float4*)x;

    float4 acc[8];
#pragma unroll
    for (int r = 0; r < 8; r++) acc[r] = make_float4(0.f, 0.f, 0.f, 0.f);

#pragma unroll 4
    for (int k4 = 0; k4 < 32; k4++) {
        float4 w0 = W4[(k4 * 4 + 0) * 32 + tx];
        float4 w1 = W4[(k4 * 4 + 1) * 32 + tx];
        float4 w2 = W4[(k4 * 4 + 2) * 32 + tx];
        float4 w3 = W4[(k4 * 4 + 3) * 32 + tx];
#pragma unroll
        for (int r = 0; r < 8; r++) {
            int gr = row0 + r;
            float4 xv = (gr < N) ? x4[gr * 32 + k4] : make_float4(0.f, 0.f, 0.f, 0.f);
            acc[r].x = fmaf(xv.x, w0.x, acc[r].x);
            acc[r].y = fmaf(xv.x, w0.y, acc[r].y);
            acc[r].z = fmaf(xv.x, w0.z, acc[r].z);
            acc[r].w = fmaf(xv.x, w0.w, acc[r].w);
            acc[r].x = fmaf(xv.y, w1.x, acc[r].x);
            acc[r].y = fmaf(xv.y, w1.y, acc[r].y);
            acc[r].z = fmaf(xv.y, w1.z, acc[r].z);
            acc[r].w = fmaf(xv.y, w1.w, acc[r].w);
            acc[r].x = fmaf(xv.z, w2.x, acc[r].x);
            acc[r].y = fmaf(xv.z, w2.y, acc[r].y);
            acc[r].z = fmaf(xv.z, w2.z, acc[r].z);
            acc[r].w = fmaf(xv.z, w2.w, acc[r].w);
            acc[r].x = fmaf(xv.w, w3.x, acc[r].x);
            acc[r].y = fmaf(xv.w, w3.y, acc[r].y);
            acc[r].z = fmaf(xv.w, w3.z, acc[r].z);
            acc[r].w = fmaf(xv.w, w3.w, acc[r].w);
        }
    }

#pragma unroll
    for (int r = 0; r < 8; r++) {
        int gr = row0 + r;
        if (gr < N) g_h[gr * 32 + tx] = acc[r];
    }
}

// -------- scan_top: single-block exclusive scan of block sums --------
__global__ void scan_top_kernel(int NB) {
    __shared__ int s[SCAN_BLK];
    int t = threadIdx.x;
    int v = (t < NB) ? g_bsum[t] : 0;
    s[t] = v;
    __syncthreads();
    for (int off = 1; off < SCAN_BLK; off <<= 1) {
        int add = (t >= off) ? s[t - off] : 0;
        __syncthreads();
        s[t] += add;
        __syncthreads();
    }
    if (t < NB) g_bsum[t] = s[t] - v;   // exclusive
}

// -------- per-block exclusive scan -> indptr, cursor, dinv --------
__global__ void scan_final_kernel(int N) {
    __shared__ int s[SCAN_BLK];
    int i = blockIdx.x * SCAN_BLK + threadIdx.x;
    int t = threadIdx.x;
    int v = (i < N) ? g_ideg[i] : 0;
    s[t] = v;
    __syncthreads();
    for (int off = 1; off < SCAN_BLK; off <<= 1) {
        int add = (t >= off) ? s[t - off] : 0;
        __syncthreads();
        s[t] += add;
        __syncthreads();
    }
    if (i < N) {
        int start = g_bsum[blockIdx.x] + s[t] - v;
        g_indptr[i] = start;
        g_cursor[i] = start;
        g_dinv[i] = rsqrtf((float)(v + 1));   // +1 self loop
    }
}

// -------- CSR fill --------
__global__ void fill_kernel(const int* __restrict__ ei, int E, int N) {
    int e = blockIdx.x * blockDim.x + threadIdx.x;
    if (e < E) {
        int row = ei[e];
        int col = ei[E + e];
        if ((unsigned)row < (unsigned)N && (unsigned)col < (unsigned)N) {
            int pos = atomicAdd(&g_cursor[col], 1);
            if ((unsigned)pos < (unsigned)EMAX) g_srcs[pos] = row;
        }
    }
}

// -------- gather: coalesced index prefetch + shfl distribution ------
#define GATHER_BLOCKS 1184
__global__ void __launch_bounds__(256) gather_kernel(
        const float* __restrict__ b, int N) {
    __shared__ float s_sum[DFEAT];
    __shared__ float s_sumsq[DFEAT];
    int tid = threadIdx.x;
    if (tid < DFEAT) { s_sum[tid] = 0.f; s_sumsq[tid] = 0.f; }
    __syncthreads();

    int lane = tid & 31;
    int warp_g = (blockIdx.x * blockDim.x + tid) >> 5;
    int nwarps = (GATHER_BLOCKS * 256) >> 5;

    float4 bb = ((const float4*)b)[lane];

    float ps0 = 0.f, ps1 = 0.f, ps2 = 0.f, ps3 = 0.f;
    float q0 = 0.f, q1 = 0.f, q2 = 0.f, q3 = 0.f;

    for (int w = warp_g; w < N; w += nwarps) {
        float di = g_dinv[w];
        int start = g_indptr[w];
        int cnt = g_ideg[w];

        // self loop + bias
        float4 a = g_h[w * 32 + lane];
        float selfn = di * di;
        a.x = fmaf(a.x, selfn, bb.x);
        a.y = fmaf(a.y, selfn, bb.y);
        a.z = fmaf(a.z, selfn, bb.z);
        a.w = fmaf(a.w, selfn, bb.w);

        // process edges in warp-sized batches: lane j preloads index+norm,
        // shfl distributes; h-row loads depend only on register shuffles.
        for (int base = 0; base < cnt; base += 32) {
            int j = base + lane;
            int src = 0;
            float nm = 0.f;
            if (j < cnt) {
                src = g_srcs[start + j];       // coalesced
                nm = di * g_dinv[src];         // lane-parallel gather
            }
            int m = cnt - base; if (m > 32) m = 32;

            int t = 0;
            for (; t + 4 <= m; t += 4) {
                int r0 = __shfl_sync(0xffffffffu, src, t + 0);
                int r1 = __shfl_sync(0xffffffffu, src, t + 1);
                int r2 = __shfl_sync(0xffffffffu, src, t + 2);
                int r3 = __shfl_sync(0xffffffffu, src, t + 3);
                float n0 = __shfl_sync(0xffffffffu, nm, t + 0);
                float n1 = __shfl_sync(0xffffffffu, nm, t + 1);
                float n2 = __shfl_sync(0xffffffffu, nm, t + 2);
                float n3 = __shfl_sync(0xffffffffu, nm, t + 3);
                float4 v0 = g_h[r0 * 32 + lane];
                float4 v1 = g_h[r1 * 32 + lane];
                float4 v2 = g_h[r2 * 32 + lane];
                float4 v3 = g_h[r3 * 32 + lane];
                a.x = fmaf(v0.x, n0, a.x); a.y = fmaf(v0.y, n0, a.y);
                a.z = fmaf(v0.z, n0, a.z); a.w = fmaf(v0.w, n0, a.w);
                a.x = fmaf(v1.x, n1, a.x); a.y = fmaf(v1.y, n1, a.y);
                a.z = fmaf(v1.z, n1, a.z); a.w = fmaf(v1.w, n1, a.w);
                a.x = fmaf(v2.x, n2, a.x); a.y = fmaf(v2.y, n2, a.y);
                a.z = fmaf(v2.z, n2, a.z); a.w = fmaf(v2.w, n2, a.w);
                a.x = fmaf(v3.x, n3, a.x); a.y = fmaf(v3.y, n3, a.y);
                a.z = fmaf(v3.z, n3, a.z); a.w = fmaf(v3.w, n3, a.w);
            }
            for (; t < m; t++) {
                int r = __shfl_sync(0xffffffffu, src, t);
                float nn = __shfl_sync(0xffffffffu, nm, t);
                float4 v = g_h[r * 32 + lane];
                a.x = fmaf(v.x, nn, a.x); a.y = fmaf(v.y, nn, a.y);
                a.z = fmaf(v.z, nn, a.z); a.w = fmaf(v.w, nn, a.w);
            }
        }

        g_acc[w * 32 + lane] = a;

        ps0 += a.x; ps1 += a.y; ps2 += a.z; ps3 += a.w;
        q0 = fmaf(a.x, a.x, q0); q1 = fmaf(a.y, a.y, q1);
        q2 = fmaf(a.z, a.z, q2); q3 = fmaf(a.w, a.w, q3);
    }

    // block-level BN partial reduction
    int c = lane * 4;
    atomicAdd(&s_sum[c + 0], ps0);
    atomicAdd(&s_sum[c + 1], ps1);
    atomicAdd(&s_sum[c + 2], ps2);
    atomicAdd(&s_sum[c + 3], ps3);
    atomicAdd(&s_sumsq[c + 0], q0);
    atomicAdd(&s_sumsq[c + 1], q1);
    atomicAdd(&s_sumsq[c + 2], q2);
    atomicAdd(&s_sumsq[c + 3], q3);
    __syncthreads();

    if (tid < DFEAT) {
        atomicAdd(&g_sum[tid], s_sum[tid]);
        atomicAdd(&g_sumsq[tid], s_sumsq[tid]);
    }
}

// -------- BN normalize + relu + residual --------
__global__ void finalize_kernel(const float* __restrict__ x,
                                const float* __restrict__ gamma,
                                const float* __restrict__ beta,
                                float* __restrict__ out, int N) {
    int i = blockIdx.x * blockDim.x + threadIdx.x;
    int total = N * 32;       // float4 units
    if (i >= total) return;
    int d4 = i & 31;
    float inv_n = 1.0f / (float)N;

    float4 a  = g_acc[i];
    float4 xv = ((const float4*)x)[i];
    float4 g  = ((const float4*)gamma)[d4];
    float4 bt = ((const float4*)beta)[d4];
    float4 sm = ((const float4*)g_sum)[d4];
    float4 sq = ((const float4*)g_sumsq)[d4];

    float4 o;
    {
        float m = sm.x * inv_n;
        float var = sq.x * inv_n - m * m;
        float v = (a.x - m) * rsqrtf(var + BN_EPS) * g.x + bt.x;
        o.x = fmaxf(v, 0.f) + xv.x;
    }
    {
        float m = sm.y * inv_n;
        float var = sq.y * inv_n - m * m;
        float v = (a.y - m) * rsqrtf(var + BN_EPS) * g.y + bt.y;
        o.y = fmaxf(v, 0.f) + xv.y;
    }
    {
        float m = sm.z * inv_n;
        float var = sq.z * inv_n - m * m;
        float v = (a.z - m) * rsqrtf(var + BN_EPS) * g.z + bt.z;
        o.z = fmaxf(v, 0.f) + xv.z;
    }
    {
        float m = sm.w * inv_n;
        float var = sq.w * inv_n - m * m;
        float v = (a.w - m) * rsqrtf(var + BN_EPS) * g.w + bt.w;
        o.w = fmaxf(v, 0.f) + xv.w;
    }
    ((float4*)out)[i] = o;
}

extern "C" void kernel_launch(void* const* d_in, const int* in_sizes, int n_in,
                              void* d_out, int out_size) {
    const float* x     = (const float*)d_in[0];
    const int*   ei    = (const int*)d_in[1];    // int32 per harness dtype set
    const float* W     = (const float*)d_in[2];
    const float* b     = (const float*)d_in[3];
    const float* gamma = (const float*)d_in[4];
    const float* beta  = (const float*)d_in[5];
    float*       out   = (float*)d_out;

    int N = in_sizes[0] / DFEAT;
    int E = in_sizes[1] / 2;
    if (E > EMAX) E = EMAX;
    int NB = (N + SCAN_BLK - 1) / SCAN_BLK;   // 196 for N=50000 (<= 256)

    init_kernel<<<(N + 255) / 256, 256>>>(N);                 // 1
    degree_kernel<<<(E + 255) / 256, 256>>>(ei, E, N);        // 2
    scan_blocksum_kernel<<<NB, SCAN_BLK>>>(N);                // 3

    dim3 gblk(32, 8);
    gemm_kernel<<<(N + 63) / 64, gblk>>>(x, W, N);            // 4 <- ncu slot

    scan_top_kernel<<<1, SCAN_BLK>>>(NB);                     // 5
    scan_final_kernel<<<NB, SCAN_BLK>>>(N);                   // 6
    fill_kernel<<<(E + 255) / 256, 256>>>(ei, E, N);          // 7
    gather_kernel<<<GATHER_BLOCKS, 256>>>(b, N);              // 8
    finalize_kernel<<<(N * 32 + 255) / 256, 256>>>(x, gamma, beta, out, N); // 9
}

// round 6
// speedup vs baseline: 1.3268x; 1.2294x over previous
#include <cuda_runtime.h>
#include <cuda_bf16.h>
#include <cstdint>

#define DFEAT 128
#define NMAX  50000
#define EMAX  800000
#define BN_EPS 1e-5f
#define SCAN_BLK 256

// -------- scratch (static device globals: no allocation) --------
__device__ float4   g_h[NMAX * 32];         // h = x @ W  (fp32 result)
__device__ float4   g_acc[NMAX * 32];       // gathered output (pre-BN)
__device__ uint32_t g_xh[NMAX * 64];        // x hi, bf16x2 packed
__device__ uint32_t g_xl[NMAX * 64];        // x lo residual, bf16x2 packed
__device__ uint32_t g_wfh[8192];            // W hi, mma B-fragment layout
__device__ uint32_t g_wfl[8192];            // W lo, mma B-fragment layout
__device__ float    g_dinv[NMAX];
__device__ int      g_ideg[NMAX];
__device__ int      g_indptr[NMAX];
__device__ int      g_cursor[NMAX];
__device__ int      g_srcs[EMAX];
__device__ int      g_bsum[SCAN_BLK];
__device__ __align__(16) float g_sum[DFEAT];
__device__ __align__(16) float g_sumsq[DFEAT];

__device__ __forceinline__ uint32_t pack_bf2(float a, float b) {
    __nv_bfloat16 ha = __float2bfloat16(a);
    __nv_bfloat16 hb = __float2bfloat16(b);
    return (uint32_t)__bfloat16_as_ushort(ha) |
           ((uint32_t)__bfloat16_as_ushort(hb) << 16);
}

// -------- 0. init --------
__global__ void init_kernel(int N) {
    int i = blockIdx.x * blockDim.x + threadIdx.x;
    if (i < N) g_ideg[i] = 0;
    if (i < DFEAT) { g_sum[i] = 0.0f; g_sumsq[i] = 0.0f; }
}

// -------- 1. split x into bf16 hi + bf16 residual --------
__global__ void split_x_kernel(const float* __restrict__ x, int N) {
    int i = blockIdx.x * blockDim.x + threadIdx.x;
    if (i >= N * 64) return;
    float2 v = ((const float2*)x)[i];
    __nv_bfloat16 hx = __float2bfloat16(v.x);
    __nv_bfloat16 hy = __float2bfloat16(v.y);
    float lx = v.x - __bfloat162float(hx);
    float ly = v.y - __bfloat162float(hy);
    g_xh[i] = (uint32_t)__bfloat16_as_ushort(hx) |
              ((uint32_t)__bfloat16_as_ushort(hy) << 16);
    g_xl[i] = pack_bf2(lx, ly);
}

// -------- 2. pack W into mma B-fragment layout (hi + lo) ------------
// idx = kh*512 + n*4 + tig, kh in [0,16): stores pair
// (W[kh*8 + tig*2][n], W[kh*8 + tig*2 + 1][n]) as bf16x2.
__global__ void pack_w_kernel(const float* __restrict__ W) {
    int tid = blockIdx.x * blockDim.x + threadIdx.x;
    if (tid >= 8192) return;
    int tig = tid & 3;
    int n = (tid >> 2) & 127;
    int kh = tid >> 9;
    int k = kh * 8 + tig * 2;
    float w0 = W[k * 128 + n];
    float w1 = W[(k + 1) * 128 + n];
    __nv_bfloat16 h0 = __float2bfloat16(w0);
    __nv_bfloat16 h1 = __float2bfloat16(w1);
    float l0 = w0 - __bfloat162float(h0);
    float l1 = w1 - __bfloat162float(h1);
    g_wfh[tid] = (uint32_t)__bfloat16_as_ushort(h0) |
                 ((uint32_t)__bfloat16_as_ushort(h1) << 16);
    g_wfl[tid] = pack_bf2(l0, l1);
}

// -------- 3. tensor-core GEMM: h = xh@Wh + xh@Wl + xl@Wh ------------
// one warp = 16 rows x full 128 cols; m16n8k16 bf16 mma, fp32 accum.
__device__ __forceinline__ void mma16816(float* d, uint32_t a0, uint32_t a1,
                                         uint32_t a2, uint32_t a3,
                                         uint32_t b0, uint32_t b1) {
    asm volatile(
        "mma.sync.aligned.m16n8k16.row.col.f32.bf16.bf16.f32 "
        "{%0,%1,%2,%3}, {%4,%5,%6,%7}, {%8,%9}, {%0,%1,%2,%3};"
        : "+f"(d[0]), "+f"(d[1]), "+f"(d[2]), "+f"(d[3])
        : "r"(a0), "r"(a1), "r"(a2), "r"(a3), "r"(b0), "r"(b1));
}

__global__ void __launch_bounds__(256) gemm_mma_kernel(int N) {
    int warp = (blockIdx.x * blockDim.x + threadIdx.x) >> 5;
    int lane = threadIdx.x & 31;
    int g = lane >> 2;
    int tig = lane & 3;
    int m0 = warp * 16;
    if (m0 >= N) return;

    float d[16][4];
#pragma unroll
    for (int nt = 0; nt < 16; nt++)
#pragma unroll
        for (int c = 0; c < 4; c++) d[nt][c] = 0.f;

    int rowA = (m0 + g) * 64;
    int rowA8 = (m0 + g + 8) * 64;

#pragma unroll
    for (int kt = 0; kt < 8; kt++) {
        int kb = kt * 8 + tig;
        uint32_t ah0 = g_xh[rowA + kb];
        uint32_t ah1 = g_xh[rowA8 + kb];
        uint32_t ah2 = g_xh[rowA + kb + 4];
        uint32_t ah3 = g_xh[rowA8 + kb + 4];
        uint32_t al0 = g_xl[rowA + kb];
        uint32_t al1 = g_xl[rowA8 + kb];
        uint32_t al2 = g_xl[rowA + kb + 4];
        uint32_t al3 = g_xl[rowA8 + kb + 4];
        int wb = kt * 1024;   // kh = kt*2 -> kh*512
#pragma unroll
        for (int nt = 0; nt < 16; nt++) {
            int nb = wb + (nt * 8 + g) * 4 + tig;
            uint32_t bh0 = g_wfh[nb];
            uint32_t bh1 = g_wfh[nb + 512];
            uint32_t bl0 = g_wfl[nb];
            uint32_t bl1 = g_wfl[nb + 512];
            mma16816(d[nt], ah0, ah1, ah2, ah3, bh0, bh1);
            mma16816(d[nt], ah0, ah1, ah2, ah3, bl0, bl1);
            mma16816(d[nt], al0, al1, al2, al3, bh0, bh1);
        }
    }

    float* h = (float*)g_h;
    int r0 = m0 + g;
    int r1 = m0 + g + 8;
#pragma unroll
    for (int nt = 0; nt < 16; nt++) {
        int c = nt * 8 + tig * 2;
        float2 lo = make_float2(d[nt][0], d[nt][1]);
        float2 hi = make_float2(d[nt][2], d[nt][3]);
        *(float2*)&h[r0 * 128 + c] = lo;
        *(float2*)&h[r1 * 128 + c] = hi;
    }
}

// -------- 4. in-degree count --------
__global__ void degree_kernel(const int* __restrict__ ei, int E, int N) {
    int e = blockIdx.x * blockDim.x + threadIdx.x;
    if (e < E) {
        int col = ei[E + e];
        if ((unsigned)col < (unsigned)N) atomicAdd(&g_ideg[col], 1);
    }
}

// -------- 5. per-block degree sums --------
__global__ void scan_blocksum_kernel(int N) {
    __shared__ int s[SCAN_BLK];
    int i = blockIdx.x * SCAN_BLK + threadIdx.x;
    s[threadIdx.x] = (i < N) ? g_ideg[i] : 0;
    __syncthreads();
    for (int off = SCAN_BLK / 2; off > 0; off >>= 1) {
        if (threadIdx.x < off) s[threadIdx.x] += s[threadIdx.x + off];
        __syncthreads();
    }
    if (threadIdx.x == 0) g_bsum[blockIdx.x] = s[0];
}

// -------- 6. single-block exclusive scan of block sums --------
__global__ void scan_top_kernel(int NB) {
    __shared__ int s[SCAN_BLK];
    int t = threadIdx.x;
    int v = (t < NB) ? g_bsum[t] : 0;
    s[t] = v;
    __syncthreads();
    for (int off = 1; off < SCAN_BLK; off <<= 1) {
        int add = (t >= off) ? s[t - off] : 0;
        __syncthreads();
        s[t] += add;
        __syncthreads();
    }
    if (t < NB) g_bsum[t] = s[t] - v;
}

// -------- 7. per-block exclusive scan -> indptr, cursor, dinv --------
__global__ void scan_final_kernel(int N) {
    __shared__ int s[SCAN_BLK];
    int i = blockIdx.x * SCAN_BLK + threadIdx.x;
    int t = threadIdx.x;
    int v = (i < N) ? g_ideg[i] : 0;
    s[t] = v;
    __syncthreads();
    for (int off = 1; off < SCAN_BLK; off <<= 1) {
        int add = (t >= off) ? s[t - off] : 0;
        __syncthreads();
        s[t] += add;
        __syncthreads();
    }
    if (i < N) {
        int start = g_bsum[blockIdx.x] + s[t] - v;
        g_indptr[i] = start;
        g_cursor[i] = start;
        g_dinv[i] = rsqrtf((float)(v + 1));
    }
}

// -------- 8. CSR fill --------
__global__ void fill_kernel(const int* __restrict__ ei, int E, int N) {
    int e = blockIdx.x * blockDim.x + threadIdx.x;
    if (e < E) {
        int row = ei[e];
        int col = ei[E + e];
        if ((unsigned)row < (unsigned)N && (unsigned)col < (unsigned)N) {
            int pos = atomicAdd(&g_cursor[col], 1);
            if ((unsigned)pos < (unsigned)EMAX) g_srcs[pos] = row;
        }
    }
}

// -------- 9. gather + fused BN stats --------
#define GATHER_BLOCKS 1184
__global__ void __launch_bounds__(256) gather_kernel(
        const float* __restrict__ b, int N) {
    __shared__ float s_sum[DFEAT];
    __shared__ float s_sumsq[DFEAT];
    int tid = threadIdx.x;
    if (tid < DFEAT) { s_sum[tid] = 0.f; s_sumsq[tid] = 0.f; }
    __syncthreads();

    int lane = tid & 31;
    int warp_g = (blockIdx.x * blockDim.x + tid) >> 5;
    int nwarps = (GATHER_BLOCKS * 256) >> 5;

    float4 bb = ((const float4*)b)[lane];

    float ps0 = 0.f, ps1 = 0.f, ps2 = 0.f, ps3 = 0.f;
    float q0 = 0.f, q1 = 0.f, q2 = 0.f, q3 = 0.f;

    for (int w = warp_g; w < N; w += nwarps) {
        float di = g_dinv[w];
        int start = g_indptr[w];
        int cnt = g_ideg[w];

        float4 a = g_h[w * 32 + lane];
        float selfn = di * di;
        a.x = fmaf(a.x, selfn, bb.x);
        a.y = fmaf(a.y, selfn, bb.y);
        a.z = fmaf(a.z, selfn, bb.z);
        a.w = fmaf(a.w, selfn, bb.w);

        for (int base = 0; base < cnt; base += 32) {
            int j = base + lane;
            int src = 0;
            float nm = 0.f;
            if (j < cnt) {
                src = g_srcs[start + j];
                nm = di * g_dinv[src];
            }
            int m = cnt - base; if (m > 32) m = 32;

            int t = 0;
            for (; t + 4 <= m; t += 4) {
                int r0 = __shfl_sync(0xffffffffu, src, t + 0);
                int r1 = __shfl_sync(0xffffffffu, src, t + 1);
                int r2 = __shfl_sync(0xffffffffu, src, t + 2);
                int r3 = __shfl_sync(0xffffffffu, src, t + 3);
                float n0 = __shfl_sync(0xffffffffu, nm, t + 0);
                float n1 = __shfl_sync(0xffffffffu, nm, t + 1);
                float n2 = __shfl_sync(0xffffffffu, nm, t + 2);
                float n3 = __shfl_sync(0xffffffffu, nm, t + 3);
                float4 v0 = g_h[r0 * 32 + lane];
                float4 v1 = g_h[r1 * 32 + lane];
                float4 v2 = g_h[r2 * 32 + lane];
                float4 v3 = g_h[r3 * 32 + lane];
                a.x = fmaf(v0.x, n0, a.x); a.y = fmaf(v0.y, n0, a.y);
                a.z = fmaf(v0.z, n0, a.z); a.w = fmaf(v0.w, n0, a.w);
                a.x = fmaf(v1.x, n1, a.x); a.y = fmaf(v1.y, n1, a.y);
                a.z = fmaf(v1.z, n1, a.z); a.w = fmaf(v1.w, n1, a.w);
                a.x = fmaf(v2.x, n2, a.x); a.y = fmaf(v2.y, n2, a.y);
                a.z = fmaf(v2.z, n2, a.z); a.w = fmaf(v2.w, n2, a.w);
                a.x = fmaf(v3.x, n3, a.x); a.y = fmaf(v3.y, n3, a.y);
                a.z = fmaf(v3.z, n3, a.z); a.w = fmaf(v3.w, n3, a.w);
            }
            for (; t < m; t++) {
                int r = __shfl_sync(0xffffffffu, src, t);
                float nn = __shfl_sync(0xffffffffu, nm, t);
                float4 v = g_h[r * 32 + lane];
                a.x = fmaf(v.x, nn, a.x); a.y = fmaf(v.y, nn, a.y);
                a.z = fmaf(v.z, nn, a.z); a.w = fmaf(v.w, nn, a.w);
            }
        }

        g_acc[w * 32 + lane] = a;

        ps0 += a.x; ps1 += a.y; ps2 += a.z; ps3 += a.w;
        q0 = fmaf(a.x, a.x, q0); q1 = fmaf(a.y, a.y, q1);
        q2 = fmaf(a.z, a.z, q2); q3 = fmaf(a.w, a.w, q3);
    }

    int c = lane * 4;
    atomicAdd(&s_sum[c + 0], ps0);
    atomicAdd(&s_sum[c + 1], ps1);
    atomicAdd(&s_sum[c + 2], ps2);
    atomicAdd(&s_sum[c + 3], ps3);
    atomicAdd(&s_sumsq[c + 0], q0);
    atomicAdd(&s_sumsq[c + 1], q1);
    atomicAdd(&s_sumsq[c + 2], q2);
    atomicAdd(&s_sumsq[c + 3], q3);
    __syncthreads();

    if (tid < DFEAT) {
        atomicAdd(&g_sum[tid], s_sum[tid]);
        atomicAdd(&g_sumsq[tid], s_sumsq[tid]);
    }
}

// -------- 10. BN normalize + relu + residual --------
__global__ void finalize_kernel(const float* __restrict__ x,
                                const float* __restrict__ gamma,
                                const float* __restrict__ beta,
                                float* __restrict__ out, int N) {
    int i = blockIdx.x * blockDim.x + threadIdx.x;
    int total = N * 32;
    if (i >= total) return;
    int d4 = i & 31;
    float inv_n = 1.0f / (float)N;

    float4 a  = g_acc[i];
    float4 xv = ((const float4*)x)[i];
    float4 g  = ((const float4*)gamma)[d4];
    float4 bt = ((const float4*)beta)[d4];
    float4 sm = ((const float4*)g_sum)[d4];
    float4 sq = ((const float4*)g_sumsq)[d4];

    float4 o;
    {
        float m = sm.x * inv_n;
        float var = sq.x * inv_n - m * m;
        float v = (a.x - m) * rsqrtf(var + BN_EPS) * g.x + bt.x;
        o.x = fmaxf(v, 0.f) + xv.x;
    }
    {
        float m = sm.y * inv_n;
        float var = sq.y * inv_n - m * m;
        float v = (a.y - m) * rsqrtf(var + BN_EPS) * g.y + bt.y;
        o.y = fmaxf(v, 0.f) + xv.y;
    }
    {
        float m = sm.z * inv_n;
        float var = sq.z * inv_n - m * m;
        float v = (a.z - m) * rsqrtf(var + BN_EPS) * g.z + bt.z;
        o.z = fmaxf(v, 0.f) + xv.z;
    }
    {
        float m = sm.w * inv_n;
        float var = sq.w * inv_n - m * m;
        float v = (a.w - m) * rsqrtf(var + BN_EPS) * g.w + bt.w;
        o.w = fmaxf(v, 0.f) + xv.w;
    }
    ((float4*)out)[i] = o;
}

extern "C" void kernel_launch(void* const* d_in, const int* in_sizes, int n_in,
                              void* d_out, int out_size) {
    const float* x     = (const float*)d_in[0];
    const int*   ei    = (const int*)d_in[1];
    const float* W     = (const float*)d_in[2];
    const float* b     = (const float*)d_in[3];
    const float* gamma = (const float*)d_in[4];
    const float* beta  = (const float*)d_in[5];
    float*       out   = (float*)d_out;

    int N = in_sizes[0] / DFEAT;
    int E = in_sizes[1] / 2;
    if (E > EMAX) E = EMAX;
    int NB = (N + SCAN_BLK - 1) / SCAN_BLK;

    int nstrips = (N + 15) / 16;
    int gemm_blocks = (nstrips + 7) / 8;   // 8 warps per block

    init_kernel<<<(N + 255) / 256, 256>>>(N);                      // 1
    split_x_kernel<<<(N * 64 + 255) / 256, 256>>>(x, N);           // 2
    pack_w_kernel<<<32, 256>>>(W);                                 // 3
    gemm_mma_kernel<<<gemm_blocks, 256>>>(N);                      // 4 <- ncu slot

    degree_kernel<<<(E + 255) / 256, 256>>>(ei, E, N);             // 5
    scan_blocksum_kernel<<<NB, SCAN_BLK>>>(N);                     // 6
    scan_top_kernel<<<1, SCAN_BLK>>>(NB);                          // 7
    scan_final_kernel<<<NB, SCAN_BLK>>>(N);                        // 8
    fill_kernel<<<(E + 255) / 256, 256>>>(ei, E, N);               // 9
    gather_kernel<<<GATHER_BLOCKS, 256>>>(b, N);                   // 10
    finalize_kernel<<<(N * 32 + 255) / 256, 256>>>(x, gamma, beta, out, N); // 11
}

// round 7
// speedup vs baseline: 1.7208x; 1.2969x over previous
#include <cuda_runtime.h>
#include <cuda_bf16.h>
#include <cstdint>

#define DFEAT 128
#define NMAX  50000
#define EMAX  800000
#define BN_EPS 1e-5f
#define SCAN_BLK 256

// -------- scratch (static device globals: no allocation) --------
__device__ float4   g_h[NMAX * 32];         // h = x @ W  (fp32 result)
__device__ float4   g_acc[NMAX * 32];       // gathered output (pre-BN)
__device__ uint32_t g_xh[NMAX * 64];        // x hi, bf16x2 packed
__device__ uint32_t g_xl[NMAX * 64];        // x lo residual, bf16x2 packed
__device__ __align__(16) uint32_t g_wfh[8192];  // W hi, mma B-fragment layout
__device__ __align__(16) uint32_t g_wfl[8192];  // W lo, mma B-fragment layout
__device__ float    g_dinv[NMAX];
__device__ int      g_ideg[NMAX];
__device__ int      g_indptr[NMAX];
__device__ int      g_cursor[NMAX];
__device__ int      g_srcs[EMAX];
__device__ int      g_bsum[SCAN_BLK];
__device__ __align__(16) float g_sum[DFEAT];
__device__ __align__(16) float g_sumsq[DFEAT];

__device__ __forceinline__ uint32_t pack_bf2(float a, float b) {
    __nv_bfloat16 ha = __float2bfloat16(a);
    __nv_bfloat16 hb = __float2bfloat16(b);
    return (uint32_t)__bfloat16_as_ushort(ha) |
           ((uint32_t)__bfloat16_as_ushort(hb) << 16);
}

// -------- 0. init --------
__global__ void init_kernel(int N) {
    int i = blockIdx.x * blockDim.x + threadIdx.x;
    if (i < N) g_ideg[i] = 0;
    if (i < DFEAT) { g_sum[i] = 0.0f; g_sumsq[i] = 0.0f; }
}

// -------- 1. split x into bf16 hi + bf16 residual --------
__global__ void split_x_kernel(const float* __restrict__ x, int N) {
    int i = blockIdx.x * blockDim.x + threadIdx.x;
    if (i >= N * 64) return;
    float2 v = ((const float2*)x)[i];
    __nv_bfloat16 hx = __float2bfloat16(v.x);
    __nv_bfloat16 hy = __float2bfloat16(v.y);
    float lx = v.x - __bfloat162float(hx);
    float ly = v.y - __bfloat162float(hy);
    g_xh[i] = (uint32_t)__bfloat16_as_ushort(hx) |
              ((uint32_t)__bfloat16_as_ushort(hy) << 16);
    g_xl[i] = pack_bf2(lx, ly);
}

// -------- 2. pack W into mma B-fragment layout (hi + lo) ------------
__global__ void pack_w_kernel(const float* __restrict__ W) {
    int tid = blockIdx.x * blockDim.x + threadIdx.x;
    if (tid >= 8192) return;
    int tig = tid & 3;
    int n = (tid >> 2) & 127;
    int kh = tid >> 9;
    int k = kh * 8 + tig * 2;
    float w0 = W[k * 128 + n];
    float w1 = W[(k + 1) * 128 + n];
    __nv_bfloat16 h0 = __float2bfloat16(w0);
    __nv_bfloat16 h1 = __float2bfloat16(w1);
    float l0 = w0 - __bfloat162float(h0);
    float l1 = w1 - __bfloat162float(h1);
    g_wfh[tid] = (uint32_t)__bfloat16_as_ushort(h0) |
                 ((uint32_t)__bfloat16_as_ushort(h1) << 16);
    g_wfl[tid] = pack_bf2(l0, l1);
}

// -------- 3. tensor-core GEMM with smem-staged W fragments ----------
__device__ __forceinline__ void mma16816(float* d, uint32_t a0, uint32_t a1,
                                         uint32_t a2, uint32_t a3,
                                         uint32_t b0, uint32_t b1) {
    asm volatile(
        "mma.sync.aligned.m16n8k16.row.col.f32.bf16.bf16.f32 "
        "{%0,%1,%2,%3}, {%4,%5,%6,%7}, {%8,%9}, {%0,%1,%2,%3};"
        : "+f"(d[0]), "+f"(d[1]), "+f"(d[2]), "+f"(d[3])
        : "r"(a0), "r"(a1), "r"(a2), "r"(a3), "r"(b0), "r"(b1));
}

__global__ void __launch_bounds__(256) gemm_mma_kernel(int N) {
    extern __shared__ uint32_t s_w[];
    uint32_t* s_wh = s_w;            // 8192 words
    uint32_t* s_wl = s_w + 8192;     // 8192 words

    // cooperative stage of both W fragment arrays (64KB)
    {
        uint4* dh = (uint4*)s_wh;
        uint4* dl = (uint4*)s_wl;
        const uint4* sh = (const uint4*)g_wfh;
        const uint4* sl = (const uint4*)g_wfl;
#pragma unroll
        for (int i = threadIdx.x; i < 2048; i += 256) {
            dh[i] = sh[i];
            dl[i] = sl[i];
        }
    }
    __syncthreads();

    int warp = (blockIdx.x * blockDim.x + threadIdx.x) >> 5;
    int lane = threadIdx.x & 31;
    int g = lane >> 2;
    int tig = lane & 3;
    int m0 = warp * 16;
    if (m0 >= N) return;

    float d[16][4];
#pragma unroll
    for (int nt = 0; nt < 16; nt++)
#pragma unroll
        for (int c = 0; c < 4; c++) d[nt][c] = 0.f;

    int rowA = (m0 + g) * 64;
    int rowA8 = (m0 + g + 8) * 64;

#pragma unroll
    for (int kt = 0; kt < 8; kt++) {
        int kb = kt * 8 + tig;
        uint32_t ah0 = g_xh[rowA + kb];
        uint32_t ah1 = g_xh[rowA8 + kb];
        uint32_t ah2 = g_xh[rowA + kb + 4];
        uint32_t ah3 = g_xh[rowA8 + kb + 4];
        uint32_t al0 = g_xl[rowA + kb];
        uint32_t al1 = g_xl[rowA8 + kb];
        uint32_t al2 = g_xl[rowA + kb + 4];
        uint32_t al3 = g_xl[rowA8 + kb + 4];
        int wb = kt * 1024;
#pragma unroll
        for (int nt = 0; nt < 16; nt++) {
            int nb = wb + (nt * 8 + g) * 4 + tig;
            uint32_t bh0 = s_wh[nb];
            uint32_t bh1 = s_wh[nb + 512];
            uint32_t bl0 = s_wl[nb];
            uint32_t bl1 = s_wl[nb + 512];
            mma16816(d[nt], ah0, ah1, ah2, ah3, bh0, bh1);
            mma16816(d[nt], ah0, ah1, ah2, ah3, bl0, bl1);
            mma16816(d[nt], al0, al1, al2, al3, bh0, bh1);
        }
    }

    float* h = (float*)g_h;
    int r0 = m0 + g;
    int r1 = m0 + g + 8;
#pragma unroll
    for (int nt = 0; nt < 16; nt++) {
        int c = nt * 8 + tig * 2;
        float2 lo = make_float2(d[nt][0], d[nt][1]);
        float2 hi = make_float2(d[nt][2], d[nt][3]);
        *(float2*)&h[r0 * 128 + c] = lo;
        *(float2*)&h[r1 * 128 + c] = hi;
    }
}

// -------- 4. in-degree count --------
__global__ void degree_kernel(const int* __restrict__ ei, int E, int N) {
    int e = blockIdx.x * blockDim.x + threadIdx.x;
    if (e < E) {
        int col = ei[E + e];
        if ((unsigned)col < (unsigned)N) atomicAdd(&g_ideg[col], 1);
    }
}

// -------- 5. per-block degree sums --------
__global__ void scan_blocksum_kernel(int N) {
    __shared__ int s[SCAN_BLK];
    int i = blockIdx.x * SCAN_BLK + threadIdx.x;
    s[threadIdx.x] = (i < N) ? g_ideg[i] : 0;
    __syncthreads();
    for (int off = SCAN_BLK / 2; off > 0; off >>= 1) {
        if (threadIdx.x < off) s[threadIdx.x] += s[threadIdx.x + off];
        __syncthreads();
    }
    if (threadIdx.x == 0) g_bsum[blockIdx.x] = s[0];
}

// -------- 6. single-block exclusive scan of block sums --------
__global__ void scan_top_kernel(int NB) {
    __shared__ int s[SCAN_BLK];
    int t = threadIdx.x;
    int v = (t < NB) ? g_bsum[t] : 0;
    s[t] = v;
    __syncthreads();
    for (int off = 1; off < SCAN_BLK; off <<= 1) {
        int add = (t >= off) ? s[t - off] : 0;
        __syncthreads();
        s[t] += add;
        __syncthreads();
    }
    if (t < NB) g_bsum[t] = s[t] - v;
}

// -------- 7. per-block exclusive scan -> indptr, cursor, dinv --------
__global__ void scan_final_kernel(int N) {
    __shared__ int s[SCAN_BLK];
    int i = blockIdx.x * SCAN_BLK + threadIdx.x;
    int t = threadIdx.x;
    int v = (i < N) ? g_ideg[i] : 0;
    s[t] = v;
    __syncthreads();
    for (int off = 1; off < SCAN_BLK; off <<= 1) {
        int add = (t >= off) ? s[t - off] : 0;
        __syncthreads();
        s[t] += add;
        __syncthreads();
    }
    if (i < N) {
        int start = g_bsum[blockIdx.x] + s[t] - v;
        g_indptr[i] = start;
        g_cursor[i] = start;
        g_dinv[i] = rsqrtf((float)(v + 1));
    }
}

// -------- 8. CSR fill --------
__global__ void fill_kernel(const int* __restrict__ ei, int E, int N) {
    int e = blockIdx.x * blockDim.x + threadIdx.x;
    if (e < E) {
        int row = ei[e];
        int col = ei[E + e];
        if ((unsigned)row < (unsigned)N && (unsigned)col < (unsigned)N) {
            int pos = atomicAdd(&g_cursor[col], 1);
            if ((unsigned)pos < (unsigned)EMAX) g_srcs[pos] = row;
        }
    }
}

// -------- 9. gather + fused BN stats --------
#define GATHER_BLOCKS 1184
__global__ void __launch_bounds__(256) gather_kernel(
        const float* __restrict__ b, int N) {
    __shared__ float s_sum[DFEAT];
    __shared__ float s_sumsq[DFEAT];
    int tid = threadIdx.x;
    if (tid < DFEAT) { s_sum[tid] = 0.f; s_sumsq[tid] = 0.f; }
    __syncthreads();

    int lane = tid & 31;
    int warp_g = (blockIdx.x * blockDim.x + tid) >> 5;
    int nwarps = (GATHER_BLOCKS * 256) >> 5;

    float4 bb = ((const float4*)b)[lane];

    float ps0 = 0.f, ps1 = 0.f, ps2 = 0.f, ps3 = 0.f;
    float q0 = 0.f, q1 = 0.f, q2 = 0.f, q3 = 0.f;

    for (int w = warp_g; w < N; w += nwarps) {
        float di = g_dinv[w];
        int start = g_indptr[w];
        int cnt = g_ideg[w];

        float4 a = g_h[w * 32 + lane];
        float selfn = di * di;
        a.x = fmaf(a.x, selfn, bb.x);
        a.y = fmaf(a.y, selfn, bb.y);
        a.z = fmaf(a.z, selfn, bb.z);
        a.w = fmaf(a.w, selfn, bb.w);

        for (int base = 0; base < cnt; base += 32) {
            int j = base + lane;
            int src = 0;
            float nm = 0.f;
            if (j < cnt) {
                src = g_srcs[start + j];
                nm = di * g_dinv[src];
            }
            int m = cnt - base; if (m > 32) m = 32;

            int t = 0;
            for (; t + 4 <= m; t += 4) {
                int r0 = __shfl_sync(0xffffffffu, src, t + 0);
                int r1 = __shfl_sync(0xffffffffu, src, t + 1);
                int r2 = __shfl_sync(0xffffffffu, src, t + 2);
                int r3 = __shfl_sync(0xffffffffu, src, t + 3);
                float n0 = __shfl_sync(0xffffffffu, nm, t + 0);
                float n1 = __shfl_sync(0xffffffffu, nm, t + 1);
                float n2 = __shfl_sync(0xffffffffu, nm, t + 2);
                float n3 = __shfl_sync(0xffffffffu, nm, t + 3);
                float4 v0 = g_h[r0 * 32 + lane];
                float4 v1 = g_h[r1 * 32 + lane];
                float4 v2 = g_h[r2 * 32 + lane];
                float4 v3 = g_h[r3 * 32 + lane];
                a.x = fmaf(v0.x, n0, a.x); a.y = fmaf(v0.y, n0, a.y);
                a.z = fmaf(v0.z, n0, a.z); a.w = fmaf(v0.w, n0, a.w);
                a.x = fmaf(v1.x, n1, a.x); a.y = fmaf(v1.y, n1, a.y);
                a.z = fmaf(v1.z, n1, a.z); a.w = fmaf(v1.w, n1, a.w);
                a.x = fmaf(v2.x, n2, a.x); a.y = fmaf(v2.y, n2, a.y);
                a.z = fmaf(v2.z, n2, a.z); a.w = fmaf(v2.w, n2, a.w);
                a.x = fmaf(v3.x, n3, a.x); a.y = fmaf(v3.y, n3, a.y);
                a.z = fmaf(v3.z, n3, a.z); a.w = fmaf(v3.w, n3, a.w);
            }
            for (; t < m; t++) {
                int r = __shfl_sync(0xffffffffu, src, t);
                float nn = __shfl_sync(0xffffffffu, nm, t);
                float4 v = g_h[r * 32 + lane];
                a.x = fmaf(v.x, nn, a.x); a.y = fmaf(v.y, nn, a.y);
                a.z = fmaf(v.z, nn, a.z); a.w = fmaf(v.w, nn, a.w);
            }
        }

        g_acc[w * 32 + lane] = a;

        ps0 += a.x; ps1 += a.y; ps2 += a.z; ps3 += a.w;
        q0 = fmaf(a.x, a.x, q0); q1 = fmaf(a.y, a.y, q1);
        q2 = fmaf(a.z, a.z, q2); q3 = fmaf(a.w, a.w, q3);
    }

    int c = lane * 4;
    atomicAdd(&s_sum[c + 0], ps0);
    atomicAdd(&s_sum[c + 1], ps1);
    atomicAdd(&s_sum[c + 2], ps2);
    atomicAdd(&s_sum[c + 3], ps3);
    atomicAdd(&s_sumsq[c + 0], q0);
    atomicAdd(&s_sumsq[c + 1], q1);
    atomicAdd(&s_sumsq[c + 2], q2);
    atomicAdd(&s_sumsq[c + 3], q3);
    __syncthreads();

    if (tid < DFEAT) {
        atomicAdd(&g_sum[tid], s_sum[tid]);
        atomicAdd(&g_sumsq[tid], s_sumsq[tid]);
    }
}

// -------- 10. BN normalize + relu + residual --------
__global__ void finalize_kernel(const float* __restrict__ x,
                                const float* __restrict__ gamma,
                                const float* __restrict__ beta,
                                float* __restrict__ out, int N) {
    int i = blockIdx.x * blockDim.x + threadIdx.x;
    int total = N * 32;
    if (i >= total) return;
    int d4 = i & 31;
    float inv_n = 1.0f / (float)N;

    float4 a  = g_acc[i];
    float4 xv = ((const float4*)x)[i];
    float4 g  = ((const float4*)gamma)[d4];
    float4 bt = ((const float4*)beta)[d4];
    float4 sm = ((const float4*)g_sum)[d4];
    float4 sq = ((const float4*)g_sumsq)[d4];

    float4 o;
    {
        float m = sm.x * inv_n;
        float var = sq.x * inv_n - m * m;
        float v = (a.x - m) * rsqrtf(var + BN_EPS) * g.x + bt.x;
        o.x = fmaxf(v, 0.f) + xv.x;
    }
    {
        float m = sm.y * inv_n;
        float var = sq.y * inv_n - m * m;
        float v = (a.y - m) * rsqrtf(var + BN_EPS) * g.y + bt.y;
        o.y = fmaxf(v, 0.f) + xv.y;
    }
    {
        float m = sm.z * inv_n;
        float var = sq.z * inv_n - m * m;
        float v = (a.z - m) * rsqrtf(var + BN_EPS) * g.z + bt.z;
        o.z = fmaxf(v, 0.f) + xv.z;
    }
    {
        float m = sm.w * inv_n;
        float var = sq.w * inv_n - m * m;
        float v = (a.w - m) * rsqrtf(var + BN_EPS) * g.w + bt.w;
        o.w = fmaxf(v, 0.f) + xv.w;
    }
    ((float4*)out)[i] = o;
}

extern "C" void kernel_launch(void* const* d_in, const int* in_sizes, int n_in,
                              void* d_out, int out_size) {
    const float* x     = (const float*)d_in[0];
    const int*   ei    = (const int*)d_in[1];
    const float* W     = (const float*)d_in[2];
    const float* b     = (const float*)d_in[3];
    const float* gamma = (const float*)d_in[4];
    const float* beta  = (const float*)d_in[5];
    float*       out   = (float*)d_out;

    int N = in_sizes[0] / DFEAT;
    int E = in_sizes[1] / 2;
    if (E > EMAX) E = EMAX;
    int NB = (N + SCAN_BLK - 1) / SCAN_BLK;

    int nstrips = (N + 15) / 16;
    int gemm_blocks = (nstrips + 7) / 8;   // 8 warps per block
    const int GEMM_SMEM = 65536;           // 64KB dynamic smem for W frags

    // opt-in >48KB dynamic smem (host attr call, not a stream op: capture-safe)
    cudaFuncSetAttribute(gemm_mma_kernel,
                         cudaFuncAttributeMaxDynamicSharedMemorySize, GEMM_SMEM);

    init_kernel<<<(N + 255) / 256, 256>>>(N);                      // 1
    split_x_kernel<<<(N * 64 + 255) / 256, 256>>>(x, N);           // 2
    pack_w_kernel<<<32, 256>>>(W);                                 // 3
    gemm_mma_kernel<<<gemm_blocks, 256, GEMM_SMEM>>>(N);           // 4 <- ncu slot

    degree_kernel<<<(E + 255) / 256, 256>>>(ei, E, N);             // 5
    scan_blocksum_kernel<<<NB, SCAN_BLK>>>(N);                     // 6
    scan_top_kernel<<<1, SCAN_BLK>>>(NB);                          // 7
    scan_final_kernel<<<NB, SCAN_BLK>>>(N);                        // 8
    fill_kernel<<<(E + 255) / 256, 256>>>(ei, E, N);               // 9
    gather_kernel<<<GATHER_BLOCKS, 256>>>(b, N);                   // 10
    finalize_kernel<<<(N * 32 + 255) / 256, 256>>>(x, gamma, beta, out, N); // 11
}

// round 9
// speedup vs baseline: 1.8588x; 1.0802x over previous
#include <cuda_runtime.h>
#include <cuda_bf16.h>
#include <cstdint>

#define DFEAT 128
#define NMAX  50000
#define EMAX  800000
#define BN_EPS 1e-5f
#define SCAN_BLK 256

// -------- scratch (static device globals: no allocation) --------
__device__ float4 g_h[NMAX * 32];           // h = x @ W  (fp32 result)
__device__ float4 g_acc[NMAX * 32];         // gathered output (pre-BN)
__device__ __align__(16) uint2 g_wfh2[4096]; // W hi frags, (bh0,bh1) adjacent
__device__ __align__(16) uint2 g_wfl2[4096]; // W lo frags, (bl0,bl1) adjacent
__device__ float  g_dinv[NMAX];
__device__ int    g_ideg[NMAX];
__device__ int    g_indptr[NMAX];
__device__ int    g_cursor[NMAX];
__device__ int    g_srcs[EMAX];
__device__ int    g_bsum[SCAN_BLK];
__device__ __align__(16) float g_sum[DFEAT];
__device__ __align__(16) float g_sumsq[DFEAT];

__device__ __forceinline__ uint32_t pack_bf2(float a, float b) {
    __nv_bfloat16 ha = __float2bfloat16(a);
    __nv_bfloat16 hb = __float2bfloat16(b);
    return (uint32_t)__bfloat16_as_ushort(ha) |
           ((uint32_t)__bfloat16_as_ushort(hb) << 16);
}

// split float2 -> bf16x2 hi + bf16x2 residual
__device__ __forceinline__ void split2(float2 v, uint32_t& hi, uint32_t& lo) {
    __nv_bfloat162 h = __float22bfloat162_rn(v);
    float2 hb = __bfloat1622float2(h);
    hi = *reinterpret_cast<uint32_t*>(&h);
    lo = pack_bf2(v.x - hb.x, v.y - hb.y);
}

// -------- 0. init --------
__global__ void init_kernel(int N) {
    int i = blockIdx.x * blockDim.x + threadIdx.x;
    if (i < N) g_ideg[i] = 0;
    if (i < DFEAT) { g_sum[i] = 0.0f; g_sumsq[i] = 0.0f; }
}

// -------- 1. in-degree count --------
__global__ void degree_kernel(const int* __restrict__ ei, int E, int N) {
    int e = blockIdx.x * blockDim.x + threadIdx.x;
    if (e < E) {
        int col = ei[E + e];
        if ((unsigned)col < (unsigned)N) atomicAdd(&g_ideg[col], 1);
    }
}

// -------- 2. pack W into paired B-fragment layout (hi + lo) ---------
// 4096 pairs total: p = kt*512 + nt*32 + g*4 + tig, pair = (kh=2kt, kh=2kt+1)
__global__ void pack_w_kernel(const float* __restrict__ W) {
    int p = blockIdx.x * blockDim.x + threadIdx.x;
    if (p >= 4096) return;                       // FIX: 4096 pairs, not 8192
    int tig = p & 3;
    int g = (p >> 2) & 7;
    int nt = (p >> 5) & 15;
    int kt = p >> 9;                             // [0, 8)
    int n = nt * 8 + g;
    uint2 wh, wl;
    uint32_t* whp = (uint32_t*)&wh;
    uint32_t* wlp = (uint32_t*)&wl;
#pragma unroll
    for (int half = 0; half < 2; half++) {
        int k = (2 * kt + half) * 8 + tig * 2;
        float w0 = W[k * 128 + n];
        float w1 = W[(k + 1) * 128 + n];
        __nv_bfloat16 h0 = __float2bfloat16(w0);
        __nv_bfloat16 h1 = __float2bfloat16(w1);
        whp[half] = (uint32_t)__bfloat16_as_ushort(h0) |
                    ((uint32_t)__bfloat16_as_ushort(h1) << 16);
        wlp[half] = pack_bf2(w0 - __bfloat162float(h0),
                             w1 - __bfloat162float(h1));
    }
    g_wfh2[p] = wh;
    g_wfl2[p] = wl;
}

// -------- 3. tensor-core GEMM, fused x split, smem W frags ----------
__device__ __forceinline__ void mma16816(float* d, uint32_t a0, uint32_t a1,
                                         uint32_t a2, uint32_t a3,
                                         uint32_t b0, uint32_t b1) {
    asm volatile(
        "mma.sync.aligned.m16n8k16.row.col.f32.bf16.bf16.f32 "
        "{%0,%1,%2,%3}, {%4,%5,%6,%7}, {%8,%9}, {%0,%1,%2,%3};"
        : "+f"(d[0]), "+f"(d[1]), "+f"(d[2]), "+f"(d[3])
        : "r"(a0), "r"(a1), "r"(a2), "r"(a3), "r"(b0), "r"(b1));
}

__global__ void __launch_bounds__(256) gemm_mma_kernel(
        const float* __restrict__ x, int N) {
    extern __shared__ uint2 s_w2[];
    uint2* s_wh = s_w2;              // 4096 uint2
    uint2* s_wl = s_w2 + 4096;       // 4096 uint2

    {   // stage 64KB of W fragments
        uint4* dh = (uint4*)s_wh;
        uint4* dl = (uint4*)s_wl;
        const uint4* sh = (const uint4*)g_wfh2;
        const uint4* sl = (const uint4*)g_wfl2;
#pragma unroll
        for (int i = threadIdx.x; i < 2048; i += 256) {
            dh[i] = sh[i];
            dl[i] = sl[i];
        }
    }
    __syncthreads();

    int warp = (blockIdx.x * blockDim.x + threadIdx.x) >> 5;
    int lane = threadIdx.x & 31;
    int g = lane >> 2;
    int tig = lane & 3;
    int m0 = warp * 16;
    if (m0 >= N) return;

    int r0i = m0 + g;       if (r0i > N - 1) r0i = N - 1;
    int r1i = m0 + g + 8;   if (r1i > N - 1) r1i = N - 1;

    float d[16][4];
#pragma unroll
    for (int nt = 0; nt < 16; nt++)
#pragma unroll
        for (int c = 0; c < 4; c++) d[nt][c] = 0.f;

    const float2* x2 = (const float2*)x;
    long long rowA = (long long)r0i * 64;
    long long rowA8 = (long long)r1i * 64;

#pragma unroll
    for (int kt = 0; kt < 8; kt++) {
        int kb = kt * 8 + tig;
        uint32_t ah0, ah1, ah2, ah3, al0, al1, al2, al3;
        split2(x2[rowA + kb], ah0, al0);
        split2(x2[rowA8 + kb], ah1, al1);
        split2(x2[rowA + kb + 4], ah2, al2);
        split2(x2[rowA8 + kb + 4], ah3, al3);
#pragma unroll
        for (int nt = 0; nt < 16; nt++) {
            int p = (kt * 16 + nt) * 32 + lane;
            uint2 bh = s_wh[p];
            uint2 bl = s_wl[p];
            mma16816(d[nt], ah0, ah1, ah2, ah3, bh.x, bh.y);
            mma16816(d[nt], ah0, ah1, ah2, ah3, bl.x, bl.y);
            mma16816(d[nt], al0, al1, al2, al3, bh.x, bh.y);
        }
    }

    float* h = (float*)g_h;
    int r0 = m0 + g;
    int r1 = m0 + g + 8;
#pragma unroll
    for (int nt = 0; nt < 16; nt++) {
        int c = nt * 8 + tig * 2;
        if (r0 < N)
            *(float2*)&h[(long long)r0 * 128 + c] = make_float2(d[nt][0], d[nt][1]);
        if (r1 < N)
            *(float2*)&h[(long long)r1 * 128 + c] = make_float2(d[nt][2], d[nt][3]);
    }
}

// -------- 4. per-block degree sums --------
__global__ void scan_blocksum_kernel(int N) {
    __shared__ int s[SCAN_BLK];
    int i = blockIdx.x * SCAN_BLK + threadIdx.x;
    s[threadIdx.x] = (i < N) ? g_ideg[i] : 0;
    __syncthreads();
    for (int off = SCAN_BLK / 2; off > 0; off >>= 1) {
        if (threadIdx.x < off) s[threadIdx.x] += s[threadIdx.x + off];
        __syncthreads();
    }
    if (threadIdx.x == 0) g_bsum[blockIdx.x] = s[0];
}

// -------- 5. merged scan: block offset by direct prefix sum ---------
__global__ void scan_final_kernel(int N, int NB) {
    __shared__ int s[SCAN_BLK];
    __shared__ int red[SCAN_BLK];
    __shared__ int s_off;
    int t = threadIdx.x;

    int part = 0;
    for (int j = t; j < blockIdx.x; j += SCAN_BLK) part += g_bsum[j];
    red[t] = part;
    __syncthreads();
    for (int off = SCAN_BLK / 2; off > 0; off >>= 1) {
        if (t < off) red[t] += red[t + off];
        __syncthreads();
    }
    if (t == 0) s_off = red[0];
    __syncthreads();

    int i = blockIdx.x * SCAN_BLK + t;
    int v = (i < N) ? g_ideg[i] : 0;
    s[t] = v;
    __syncthreads();
    for (int off = 1; off < SCAN_BLK; off <<= 1) {
        int add = (t >= off) ? s[t - off] : 0;
        __syncthreads();
        s[t] += add;
        __syncthreads();
    }
    if (i < N) {
        int start = s_off + s[t] - v;
        g_indptr[i] = start;
        g_cursor[i] = start;
        g_dinv[i] = rsqrtf((float)(v + 1));
    }
}

// -------- 6. CSR fill --------
__global__ void fill_kernel(const int* __restrict__ ei, int E, int N) {
    int e = blockIdx.x * blockDim.x + threadIdx.x;
    if (e < E) {
        int row = ei[e];
        int col = ei[E + e];
        if ((unsigned)row < (unsigned)N && (unsigned)col < (unsigned)N) {
            int pos = atomicAdd(&g_cursor[col], 1);
            if ((unsigned)pos < (unsigned)EMAX) g_srcs[pos] = row;
        }
    }
}

// -------- 7. gather + fused BN stats --------
#define GATHER_BLOCKS 1184
__global__ void __launch_bounds__(256) gather_kernel(
        const float* __restrict__ b, int N) {
    __shared__ float s_sum[DFEAT];
    __shared__ float s_sumsq[DFEAT];
    int tid = threadIdx.x;
    if (tid < DFEAT) { s_sum[tid] = 0.f; s_sumsq[tid] = 0.f; }
    __syncthreads();

    int lane = tid & 31;
    int warp_g = (blockIdx.x * blockDim.x + tid) >> 5;
    int nwarps = (GATHER_BLOCKS * 256) >> 5;

    float4 bb = ((const float4*)b)[lane];

    float ps0 = 0.f, ps1 = 0.f, ps2 = 0.f, ps3 = 0.f;
    float q0 = 0.f, q1 = 0.f, q2 = 0.f, q3 = 0.f;

    for (int w = warp_g; w < N; w += nwarps) {
        float di = g_dinv[w];
        int start = g_indptr[w];
        int cnt = g_ideg[w];

        float4 a = __ldg(&g_h[w * 32 + lane]);
        float selfn = di * di;
        a.x = fmaf(a.x, selfn, bb.x);
        a.y = fmaf(a.y, selfn, bb.y);
        a.z = fmaf(a.z, selfn, bb.z);
        a.w = fmaf(a.w, selfn, bb.w);

        for (int base = 0; base < cnt; base += 32) {
            int j = base + lane;
            int src = 0;
            float nm = 0.f;
            if (j < cnt) {
                src = g_srcs[start + j];
                nm = di * g_dinv[src];
            }
            int m = cnt - base; if (m > 32) m = 32;

            int t = 0;
            for (; t + 4 <= m; t += 4) {
                int r0 = __shfl_sync(0xffffffffu, src, t + 0);
                int r1 = __shfl_sync(0xffffffffu, src, t + 1);
                int r2 = __shfl_sync(0xffffffffu, src, t + 2);
                int r3 = __shfl_sync(0xffffffffu, src, t + 3);
                float n0 = __shfl_sync(0xffffffffu, nm, t + 0);
                float n1 = __shfl_sync(0xffffffffu, nm, t + 1);
                float n2 = __shfl_sync(0xffffffffu, nm, t + 2);
                float n3 = __shfl_sync(0xffffffffu, nm, t + 3);
                float4 v0 = __ldg(&g_h[r0 * 32 + lane]);
                float4 v1 = __ldg(&g_h[r1 * 32 + lane]);
                float4 v2 = __ldg(&g_h[r2 * 32 + lane]);
                float4 v3 = __ldg(&g_h[r3 * 32 + lane]);
                a.x = fmaf(v0.x, n0, a.x); a.y = fmaf(v0.y, n0, a.y);
                a.z = fmaf(v0.z, n0, a.z); a.w = fmaf(v0.w, n0, a.w);
                a.x = fmaf(v1.x, n1, a.x); a.y = fmaf(v1.y, n1, a.y);
                a.z = fmaf(v1.z, n1, a.z); a.w = fmaf(v1.w, n1, a.w);
                a.x = fmaf(v2.x, n2, a.x); a.y = fmaf(v2.y, n2, a.y);
                a.z = fmaf(v2.z, n2, a.z); a.w = fmaf(v2.w, n2, a.w);
                a.x = fmaf(v3.x, n3, a.x); a.y = fmaf(v3.y, n3, a.y);
                a.z = fmaf(v3.z, n3, a.z); a.w = fmaf(v3.w, n3, a.w);
            }
            for (; t < m; t++) {
                int r = __shfl_sync(0xffffffffu, src, t);
                float nn = __shfl_sync(0xffffffffu, nm, t);
                float4 v = __ldg(&g_h[r * 32 + lane]);
                a.x = fmaf(v.x, nn, a.x); a.y = fmaf(v.y, nn, a.y);
                a.z = fmaf(v.z, nn, a.z); a.w = fmaf(v.w, nn, a.w);
            }
        }

        g_acc[w * 32 + lane] = a;

        ps0 += a.x; ps1 += a.y; ps2 += a.z; ps3 += a.w;
        q0 = fmaf(a.x, a.x, q0); q1 = fmaf(a.y, a.y, q1);
        q2 = fmaf(a.z, a.z, q2); q3 = fmaf(a.w, a.w, q3);
    }

    int c = lane * 4;
    atomicAdd(&s_sum[c + 0], ps0);
    atomicAdd(&s_sum[c + 1], ps1);
    atomicAdd(&s_sum[c + 2], ps2);
    atomicAdd(&s_sum[c + 3], ps3);
    atomicAdd(&s_sumsq[c + 0], q0);
    atomicAdd(&s_sumsq[c + 1], q1);
    atomicAdd(&s_sumsq[c + 2], q2);
    atomicAdd(&s_sumsq[c + 3], q3);
    __syncthreads();

    if (tid < DFEAT) {
        atomicAdd(&g_sum[tid], s_sum[tid]);
        atomicAdd(&g_sumsq[tid], s_sumsq[tid]);
    }
}

// -------- 8. BN normalize + relu + residual --------
__global__ void finalize_kernel(const float* __restrict__ x,
                                const float* __restrict__ gamma,
                                const float* __restrict__ beta,
                                float* __restrict__ out, int N) {
    int i = blockIdx.x * blockDim.x + threadIdx.x;
    int total = N * 32;
    if (i >= total) return;
    int d4 = i & 31;
    float inv_n = 1.0f / (float)N;

    float4 a  = g_acc[i];
    float4 xv = ((const float4*)x)[i];
    float4 g  = ((const float4*)gamma)[d4];
    float4 bt = ((const float4*)beta)[d4];
    float4 sm = ((const float4*)g_sum)[d4];
    float4 sq = ((const float4*)g_sumsq)[d4];

    float4 o;
    {
        float m = sm.x * inv_n;
        float var = sq.x * inv_n - m * m;
        float v = (a.x - m) * rsqrtf(var + BN_EPS) * g.x + bt.x;
        o.x = fmaxf(v, 0.f) + xv.x;
    }
    {
        float m = sm.y * inv_n;
        float var = sq.y * inv_n - m * m;
        float v = (a.y - m) * rsqrtf(var + BN_EPS) * g.y + bt.y;
        o.y = fmaxf(v, 0.f) + xv.y;
    }
    {
        float m = sm.z * inv_n;
        float var = sq.z * inv_n - m * m;
        float v = (a.z - m) * rsqrtf(var + BN_EPS) * g.z + bt.z;
        o.z = fmaxf(v, 0.f) + xv.z;
    }
    {
        float m = sm.w * inv_n;
        float var = sq.w * inv_n - m * m;
        float v = (a.w - m) * rsqrtf(var + BN_EPS) * g.w + bt.w;
        o.w = fmaxf(v, 0.f) + xv.w;
    }
    ((float4*)out)[i] = o;
}

extern "C" void kernel_launch(void* const* d_in, const int* in_sizes, int n_in,
                              void* d_out, int out_size) {
    const float* x     = (const float*)d_in[0];
    const int*   ei    = (const int*)d_in[1];
    const float* W     = (const float*)d_in[2];
    const float* b     = (const float*)d_in[3];
    const float* gamma = (const float*)d_in[4];
    const float* beta  = (const float*)d_in[5];
    float*       out   = (float*)d_out;

    int N = in_sizes[0] / DFEAT;
    int E = in_sizes[1] / 2;
    if (E > EMAX) E = EMAX;
    int NB = (N + SCAN_BLK - 1) / SCAN_BLK;

    int nstrips = (N + 15) / 16;
    int gemm_blocks = (nstrips + 7) / 8;
    const int GEMM_SMEM = 65536;

    cudaFuncSetAttribute(gemm_mma_kernel,
                         cudaFuncAttributeMaxDynamicSharedMemorySize, GEMM_SMEM);

    init_kernel<<<(N + 255) / 256, 256>>>(N);                      // 1
    degree_kernel<<<(E + 255) / 256, 256>>>(ei, E, N);             // 2
    pack_w_kernel<<<16, 256>>>(W);                                 // 3 (4096 pairs)
    gemm_mma_kernel<<<gemm_blocks, 256, GEMM_SMEM>>>(x, N);        // 4 <- ncu slot

    scan_blocksum_kernel<<<NB, SCAN_BLK>>>(N);                     // 5
    scan_final_kernel<<<NB, SCAN_BLK>>>(N, NB);                    // 6
    fill_kernel<<<(E + 255) / 256, 256>>>(ei, E, N);               // 7
    gather_kernel<<<GATHER_BLOCKS, 256>>>(b, N);                   // 8
    finalize_kernel<<<(N * 32 + 255) / 256, 256>>>(x, gamma, beta, out, N); // 9
}

// round 10
// speedup vs baseline: 1.9305x; 1.0386x over previous
#include <cuda_runtime.h>
#include <cuda_bf16.h>
#include <cstdint>

#define DFEAT 128
#define NMAX  50000
#define EMAX  800000
#define BN_EPS 1e-5f
#define SCAN_BLK 256

// -------- scratch (static device globals: no allocation) --------
__device__ float4 g_h[NMAX * 32];           // h = x @ W  (fp32 result)
__device__ float4 g_acc[NMAX * 32];         // gathered output (pre-BN)
__device__ __align__(16) uint2 g_wfh2[4096]; // W hi frags, (bh0,bh1) adjacent
__device__ __align__(16) uint2 g_wfl2[4096]; // W lo frags, (bl0,bl1) adjacent
__device__ float  g_dinv[NMAX];
__device__ __align__(16) int g_ideg[NMAX];
__device__ int    g_indptr[NMAX];
__device__ int    g_cursor[NMAX];
__device__ int    g_srcs[EMAX];
__device__ __align__(16) float g_sum[DFEAT];
__device__ __align__(16) float g_sumsq[DFEAT];

__device__ __forceinline__ uint32_t pack_bf2(float a, float b) {
    __nv_bfloat16 ha = __float2bfloat16(a);
    __nv_bfloat16 hb = __float2bfloat16(b);
    return (uint32_t)__bfloat16_as_ushort(ha) |
           ((uint32_t)__bfloat16_as_ushort(hb) << 16);
}

// split float2 -> bf16x2 hi + bf16x2 residual
__device__ __forceinline__ void split2(float2 v, uint32_t& hi, uint32_t& lo) {
    __nv_bfloat162 h = __float22bfloat162_rn(v);
    float2 hb = __bfloat1622float2(h);
    hi = *reinterpret_cast<uint32_t*>(&h);
    lo = pack_bf2(v.x - hb.x, v.y - hb.y);
}

// -------- 1. init --------
__global__ void init_kernel(int N) {
    int i = blockIdx.x * blockDim.x + threadIdx.x;
    if (i < N) g_ideg[i] = 0;
    if (i < DFEAT) { g_sum[i] = 0.0f; g_sumsq[i] = 0.0f; }
}

// -------- 2. pack W into paired B-fragment layout (hi + lo) ---------
// 4096 pairs: p = kt*512 + nt*32 + g*4 + tig, pair = (kh=2kt, kh=2kt+1)
__global__ void pack_w_kernel(const float* __restrict__ W) {
    int p = blockIdx.x * blockDim.x + threadIdx.x;
    if (p >= 4096) return;
    int tig = p & 3;
    int g = (p >> 2) & 7;
    int nt = (p >> 5) & 15;
    int kt = p >> 9;
    int n = nt * 8 + g;
    uint2 wh, wl;
    uint32_t* whp = (uint32_t*)&wh;
    uint32_t* wlp = (uint32_t*)&wl;
#pragma unroll
    for (int half = 0; half < 2; half++) {
        int k = (2 * kt + half) * 8 + tig * 2;
        float w0 = W[k * 128 + n];
        float w1 = W[(k + 1) * 128 + n];
        __nv_bfloat16 h0 = __float2bfloat16(w0);
        __nv_bfloat16 h1 = __float2bfloat16(w1);
        whp[half] = (uint32_t)__bfloat16_as_ushort(h0) |
                    ((uint32_t)__bfloat16_as_ushort(h1) << 16);
        wlp[half] = pack_bf2(w0 - __bfloat162float(h0),
                             w1 - __bfloat162float(h1));
    }
    g_wfh2[p] = wh;
    g_wfl2[p] = wl;
}

// -------- 3. FUSED: tensor-core GEMM (blocks < gemm_blocks) + degree ----
__device__ __forceinline__ void mma16816(float* d, uint32_t a0, uint32_t a1,
                                         uint32_t a2, uint32_t a3,
                                         uint32_t b0, uint32_t b1) {
    asm volatile(
        "mma.sync.aligned.m16n8k16.row.col.f32.bf16.bf16.f32 "
        "{%0,%1,%2,%3}, {%4,%5,%6,%7}, {%8,%9}, {%0,%1,%2,%3};"
        : "+f"(d[0]), "+f"(d[1]), "+f"(d[2]), "+f"(d[3])
        : "r"(a0), "r"(a1), "r"(a2), "r"(a3), "r"(b0), "r"(b1));
}

__global__ void __launch_bounds__(256) gemm_degree_kernel(
        const float* __restrict__ x, const int* __restrict__ ei,
        int E, int N, int gemm_blocks) {
    // ---- degree blocks: run in slots left free by the gemm tail ----
    if (blockIdx.x >= gemm_blocks) {
        int base = (blockIdx.x - gemm_blocks) * blockDim.x + threadIdx.x;
        int stride = (gridDim.x - gemm_blocks) * blockDim.x;
        for (int e = base; e < E; e += stride) {
            int col = ei[E + e];
            if ((unsigned)col < (unsigned)N) atomicAdd(&g_ideg[col], 1);
        }
        return;
    }

    // ---- gemm blocks ----
    extern __shared__ uint2 s_w2[];
    uint2* s_wh = s_w2;              // 4096 uint2
    uint2* s_wl = s_w2 + 4096;       // 4096 uint2

    {   // stage 64KB of W fragments
        uint4* dh = (uint4*)s_wh;
        uint4* dl = (uint4*)s_wl;
        const uint4* sh = (const uint4*)g_wfh2;
        const uint4* sl = (const uint4*)g_wfl2;
#pragma unroll
        for (int i = threadIdx.x; i < 2048; i += 256) {
            dh[i] = sh[i];
            dl[i] = sl[i];
        }
    }
    __syncthreads();

    int warp = (blockIdx.x * blockDim.x + threadIdx.x) >> 5;
    int lane = threadIdx.x & 31;
    int g = lane >> 2;
    int tig = lane & 3;
    int m0 = warp * 16;
    if (m0 >= N) return;

    int r0i = m0 + g;       if (r0i > N - 1) r0i = N - 1;
    int r1i = m0 + g + 8;   if (r1i > N - 1) r1i = N - 1;

    float d[16][4];
#pragma unroll
    for (int nt = 0; nt < 16; nt++)
#pragma unroll
        for (int c = 0; c < 4; c++) d[nt][c] = 0.f;

    const float2* x2 = (const float2*)x;
    long long rowA = (long long)r0i * 64;
    long long rowA8 = (long long)r1i * 64;

#pragma unroll
    for (int kt = 0; kt < 8; kt++) {
        int kb = kt * 8 + tig;
        uint32_t ah0, ah1, ah2, ah3, al0, al1, al2, al3;
        split2(x2[rowA + kb], ah0, al0);
        split2(x2[rowA8 + kb], ah1, al1);
        split2(x2[rowA + kb + 4], ah2, al2);
        split2(x2[rowA8 + kb + 4], ah3, al3);
#pragma unroll
        for (int nt = 0; nt < 16; nt++) {
            int p = (kt * 16 + nt) * 32 + lane;
            uint2 bh = s_wh[p];
            uint2 bl = s_wl[p];
            mma16816(d[nt], ah0, ah1, ah2, ah3, bh.x, bh.y);
            mma16816(d[nt], ah0, ah1, ah2, ah3, bl.x, bl.y);
            mma16816(d[nt], al0, al1, al2, al3, bh.x, bh.y);
        }
    }

    float* h = (float*)g_h;
    int r0 = m0 + g;
    int r1 = m0 + g + 8;
#pragma unroll
    for (int nt = 0; nt < 16; nt++) {
        int c = nt * 8 + tig * 2;
        if (r0 < N)
            *(float2*)&h[(long long)r0 * 128 + c] = make_float2(d[nt][0], d[nt][1]);
        if (r1 < N)
            *(float2*)&h[(long long)r1 * 128 + c] = make_float2(d[nt][2], d[nt][3]);
    }
}

// -------- 4. merged scan: offset by direct int4 reduce of g_ideg ----
__global__ void scan_kernel(int N) {
    __shared__ int s[SCAN_BLK];
    __shared__ int red[SCAN_BLK];
    __shared__ int s_off;
    int t = threadIdx.x;

    // offset = sum of g_ideg[0 .. blockIdx.x*256), int4-vectorized
    int limit4 = (blockIdx.x * SCAN_BLK) >> 2;   // multiple of 64
    const int4* d4 = (const int4*)g_ideg;
    int part = 0;
    for (int j = t; j < limit4; j += SCAN_BLK) {
        int4 v = d4[j];
        part += v.x + v.y + v.z + v.w;
    }
    red[t] = part;
    __syncthreads();
    for (int off = SCAN_BLK / 2; off > 0; off >>= 1) {
        if (t < off) red[t] += red[t + off];
        __syncthreads();
    }
    if (t == 0) s_off = red[0];
    __syncthreads();

    int i = blockIdx.x * SCAN_BLK + t;
    int v = (i < N) ? g_ideg[i] : 0;
    s[t] = v;
    __syncthreads();
    for (int off = 1; off < SCAN_BLK; off <<= 1) {
        int add = (t >= off) ? s[t - off] : 0;
        __syncthreads();
        s[t] += add;
        __syncthreads();
    }
    if (i < N) {
        int start = s_off + s[t] - v;
        g_indptr[i] = start;
        g_cursor[i] = start;
        g_dinv[i] = rsqrtf((float)(v + 1));
    }
}

// -------- 5. CSR fill --------
__global__ void fill_kernel(const int* __restrict__ ei, int E, int N) {
    int e = blockIdx.x * blockDim.x + threadIdx.x;
    if (e < E) {
        int row = ei[e];
        int col = ei[E + e];
        if ((unsigned)row < (unsigned)N && (unsigned)col < (unsigned)N) {
            int pos = atomicAdd(&g_cursor[col], 1);
            if ((unsigned)pos < (unsigned)EMAX) g_srcs[pos] = row;
        }
    }
}

// -------- 6. gather + fused BN stats --------
#define GATHER_BLOCKS 1184
__global__ void __launch_bounds__(256) gather_kernel(
        const float* __restrict__ b, int N) {
    __shared__ float s_sum[DFEAT];
    __shared__ float s_sumsq[DFEAT];
    int tid = threadIdx.x;
    if (tid < DFEAT) { s_sum[tid] = 0.f; s_sumsq[tid] = 0.f; }
    __syncthreads();

    int lane = tid & 31;
    int warp_g = (blockIdx.x * blockDim.x + tid) >> 5;
    int nwarps = (GATHER_BLOCKS * 256) >> 5;

    float4 bb = ((const float4*)b)[lane];

    float ps0 = 0.f, ps1 = 0.f, ps2 = 0.f, ps3 = 0.f;
    float q0 = 0.f, q1 = 0.f, q2 = 0.f, q3 = 0.f;

    for (int w = warp_g; w < N; w += nwarps) {
        float di = g_dinv[w];
        int start = g_indptr[w];
        int cnt = g_ideg[w];

        float4 a = __ldg(&g_h[w * 32 + lane]);
        float selfn = di * di;
        a.x = fmaf(a.x, selfn, bb.x);
        a.y = fmaf(a.y, selfn, bb.y);
        a.z = fmaf(a.z, selfn, bb.z);
        a.w = fmaf(a.w, selfn, bb.w);

        for (int base = 0; base < cnt; base += 32) {
            int j = base + lane;
            int src = 0;
            float nm = 0.f;
            if (j < cnt) {
                src = g_srcs[start + j];
                nm = di * g_dinv[src];
            }
            int m = cnt - base; if (m > 32) m = 32;

            int t = 0;
            for (; t + 4 <= m; t += 4) {
                int r0 = __shfl_sync(0xffffffffu, src, t + 0);
                int r1 = __shfl_sync(0xffffffffu, src, t + 1);
                int r2 = __shfl_sync(0xffffffffu, src, t + 2);
                int r3 = __shfl_sync(0xffffffffu, src, t + 3);
                float n0 = __shfl_sync(0xffffffffu, nm, t + 0);
                float n1 = __shfl_sync(0xffffffffu, nm, t + 1);
                float n2 = __shfl_sync(0xffffffffu, nm, t + 2);
                float n3 = __shfl_sync(0xffffffffu, nm, t + 3);
                float4 v0 = __ldg(&g_h[r0 * 32 + lane]);
                float4 v1 = __ldg(&g_h[r1 * 32 + lane]);
                float4 v2 = __ldg(&g_h[r2 * 32 + lane]);
                float4 v3 = __ldg(&g_h[r3 * 32 + lane]);
                a.x = fmaf(v0.x, n0, a.x); a.y = fmaf(v0.y, n0, a.y);
                a.z = fmaf(v0.z, n0, a.z); a.w = fmaf(v0.w, n0, a.w);
                a.x = fmaf(v1.x, n1, a.x); a.y = fmaf(v1.y, n1, a.y);
                a.z = fmaf(v1.z, n1, a.z); a.w = fmaf(v1.w, n1, a.w);
                a.x = fmaf(v2.x, n2, a.x); a.y = fmaf(v2.y, n2, a.y);
                a.z = fmaf(v2.z, n2, a.z); a.w = fmaf(v2.w, n2, a.w);
                a.x = fmaf(v3.x, n3, a.x); a.y = fmaf(v3.y, n3, a.y);
                a.z = fmaf(v3.z, n3, a.z); a.w = fmaf(v3.w, n3, a.w);
            }
            for (; t < m; t++) {
                int r = __shfl_sync(0xffffffffu, src, t);
                float nn = __shfl_sync(0xffffffffu, nm, t);
                float4 v = __ldg(&g_h[r * 32 + lane]);
                a.x = fmaf(v.x, nn, a.x); a.y = fmaf(v.y, nn, a.y);
                a.z = fmaf(v.z, nn, a.z); a.w = fmaf(v.w, nn, a.w);
            }
        }

        g_acc[w * 32 + lane] = a;

        ps0 += a.x; ps1 += a.y; ps2 += a.z; ps3 += a.w;
        q0 = fmaf(a.x, a.x, q0); q1 = fmaf(a.y, a.y, q1);
        q2 = fmaf(a.z, a.z, q2); q3 = fmaf(a.w, a.w, q3);
    }

    int c = lane * 4;
    atomicAdd(&s_sum[c + 0], ps0);
    atomicAdd(&s_sum[c + 1], ps1);
    atomicAdd(&s_sum[c + 2], ps2);
    atomicAdd(&s_sum[c + 3], ps3);
    atomicAdd(&s_sumsq[c + 0], q0);
    atomicAdd(&s_sumsq[c + 1], q1);
    atomicAdd(&s_sumsq[c + 2], q2);
    atomicAdd(&s_sumsq[c + 3], q3);
    __syncthreads();

    if (tid < DFEAT) {
        atomicAdd(&g_sum[tid], s_sum[tid]);
        atomicAdd(&g_sumsq[tid], s_sumsq[tid]);
    }
}

// -------- 7. BN normalize + relu + residual --------
__global__ void finalize_kernel(const float* __restrict__ x,
                                const float* __restrict__ gamma,
                                const float* __restrict__ beta,
                                float* __restrict__ out, int N) {
    int i = blockIdx.x * blockDim.x + threadIdx.x;
    int total = N * 32;
    if (i >= total) return;
    int d4 = i & 31;
    float inv_n = 1.0f / (float)N;

    float4 a  = g_acc[i];
    float4 xv = ((const float4*)x)[i];
    float4 g  = ((const float4*)gamma)[d4];
    float4 bt = ((const float4*)beta)[d4];
    float4 sm = ((const float4*)g_sum)[d4];
    float4 sq = ((const float4*)g_sumsq)[d4];

    float4 o;
    {
        float m = sm.x * inv_n;
        float var = sq.x * inv_n - m * m;
        float v = (a.x - m) * rsqrtf(var + BN_EPS) * g.x + bt.x;
        o.x = fmaxf(v, 0.f) + xv.x;
    }
    {
        float m = sm.y * inv_n;
        float var = sq.y * inv_n - m * m;
        float v = (a.y - m) * rsqrtf(var + BN_EPS) * g.y + bt.y;
        o.y = fmaxf(v, 0.f) + xv.y;
    }
    {
        float m = sm.z * inv_n;
        float var = sq.z * inv_n - m * m;
        float v = (a.z - m) * rsqrtf(var + BN_EPS) * g.z + bt.z;
        o.z = fmaxf(v, 0.f) + xv.z;
    }
    {
        float m = sm.w * inv_n;
        float var = sq.w * inv_n - m * m;
        float v = (a.w - m) * rsqrtf(var + BN_EPS) * g.w + bt.w;
        o.w = fmaxf(v, 0.f) + xv.w;
    }
    ((float4*)out)[i] = o;
}

extern "C" void kernel_launch(void* const* d_in, const int* in_sizes, int n_in,
                              void* d_out, int out_size) {
    const float* x     = (const float*)d_in[0];
    const int*   ei    = (const int*)d_in[1];
    const float* W     = (const float*)d_in[2];
    const float* b     = (const float*)d_in[3];
    const float* gamma = (const float*)d_in[4];
    const float* beta  = (const float*)d_in[5];
    float*       out   = (float*)d_out;

    int N = in_sizes[0] / DFEAT;
    int E = in_sizes[1] / 2;
    if (E > EMAX) E = EMAX;
    int NB = (N + SCAN_BLK - 1) / SCAN_BLK;

    int nstrips = (N + 15) / 16;
    int gemm_blocks = (nstrips + 7) / 8;   // 391
    int deg_blocks = 512;                  // appended; hidden in gemm tail
    const int GEMM_SMEM = 65536;

    cudaFuncSetAttribute(gemm_degree_kernel,
                         cudaFuncAttributeMaxDynamicSharedMemorySize, GEMM_SMEM);

    init_kernel<<<(N + 255) / 256, 256>>>(N);                            // 1
    pack_w_kernel<<<16, 256>>>(W);                                       // 2
    gemm_degree_kernel<<<gemm_blocks + deg_blocks, 256, GEMM_SMEM>>>(
        x, ei, E, N, gemm_blocks);                                       // 3
    scan_kernel<<<NB, SCAN_BLK>>>(N);                                    // 4
    fill_kernel<<<(E + 255) / 256, 256>>>(ei, E, N);                     // 5
    gather_kernel<<<GATHER_BLOCKS, 256>>>(b, N);                         // 6
    finalize_kernel<<<(N * 32 + 255) / 256, 256>>>(x, gamma, beta, out, N); // 7
}

// round 11
// speedup vs baseline: 2.0003x; 1.0362x over previous
#include <cuda_runtime.h>
#include <cuda_bf16.h>
#include <cstdint>

#define DFEAT 128
#define NMAX  50000
#define EMAX  800000
#define BN_EPS 1e-5f
#define SCAN_BLK 256

// -------- scratch (static device globals: no allocation) --------
__device__ float4 g_h[NMAX * 32];           // h = x @ W  (fp32 result)
__device__ float4 g_acc[NMAX * 32];         // gathered output (pre-BN)
__device__ __align__(16) uint2 g_wfh2[4096]; // W hi frags, (bh0,bh1) adjacent
__device__ __align__(16) uint2 g_wfl2[4096]; // W lo frags, (bl0,bl1) adjacent
__device__ float  g_dinv[NMAX];
__device__ __align__(16) int g_ideg[NMAX];
__device__ int    g_indptr[NMAX];
__device__ int    g_cursor[NMAX];
__device__ int    g_srcs[EMAX];
__device__ int    g_bsum[SCAN_BLK];
__device__ __align__(16) float g_sum[DFEAT];
__device__ __align__(16) float g_sumsq[DFEAT];

__device__ __forceinline__ uint32_t pack_bf2(float a, float b) {
    __nv_bfloat16 ha = __float2bfloat16(a);
    __nv_bfloat16 hb = __float2bfloat16(b);
    return (uint32_t)__bfloat16_as_ushort(ha) |
           ((uint32_t)__bfloat16_as_ushort(hb) << 16);
}

// split float2 -> bf16x2 hi + bf16x2 residual
__device__ __forceinline__ void split2(float2 v, uint32_t& hi, uint32_t& lo) {
    __nv_bfloat162 h = __float22bfloat162_rn(v);
    float2 hb = __bfloat1622float2(h);
    hi = *reinterpret_cast<uint32_t*>(&h);
    lo = pack_bf2(v.x - hb.x, v.y - hb.y);
}

// -------- 1. init --------
__global__ void init_kernel(int N) {
    int i = blockIdx.x * blockDim.x + threadIdx.x;
    if (i < N) g_ideg[i] = 0;
    if (i < DFEAT) { g_sum[i] = 0.0f; g_sumsq[i] = 0.0f; }
}

// -------- 2. pack W into paired B-fragment layout (hi + lo) ---------
__global__ void pack_w_kernel(const float* __restrict__ W) {
    int p = blockIdx.x * blockDim.x + threadIdx.x;
    if (p >= 4096) return;
    int tig = p & 3;
    int g = (p >> 2) & 7;
    int nt = (p >> 5) & 15;
    int kt = p >> 9;
    int n = nt * 8 + g;
    uint2 wh, wl;
    uint32_t* whp = (uint32_t*)&wh;
    uint32_t* wlp = (uint32_t*)&wl;
#pragma unroll
    for (int half = 0; half < 2; half++) {
        int k = (2 * kt + half) * 8 + tig * 2;
        float w0 = W[k * 128 + n];
        float w1 = W[(k + 1) * 128 + n];
        __nv_bfloat16 h0 = __float2bfloat16(w0);
        __nv_bfloat16 h1 = __float2bfloat16(w1);
        whp[half] = (uint32_t)__bfloat16_as_ushort(h0) |
                    ((uint32_t)__bfloat16_as_ushort(h1) << 16);
        wlp[half] = pack_bf2(w0 - __bfloat162float(h0),
                             w1 - __bfloat162float(h1));
    }
    g_wfh2[p] = wh;
    g_wfl2[p] = wl;
}

// -------- 3. FUSED: tensor-core GEMM (blocks < gemm_blocks) + degree ----
__device__ __forceinline__ void mma16816(float* d, uint32_t a0, uint32_t a1,
                                         uint32_t a2, uint32_t a3,
                                         uint32_t b0, uint32_t b1) {
    asm volatile(
        "mma.sync.aligned.m16n8k16.row.col.f32.bf16.bf16.f32 "
        "{%0,%1,%2,%3}, {%4,%5,%6,%7}, {%8,%9}, {%0,%1,%2,%3};"
        : "+f"(d[0]), "+f"(d[1]), "+f"(d[2]), "+f"(d[3])
        : "r"(a0), "r"(a1), "r"(a2), "r"(a3), "r"(b0), "r"(b1));
}

__global__ void __launch_bounds__(256) gemm_degree_kernel(
        const float* __restrict__ x, const int* __restrict__ ei,
        int E, int N, int gemm_blocks) {
    // ---- degree blocks: run in slots left free by the gemm tail ----
    if (blockIdx.x >= gemm_blocks) {
        int base = (blockIdx.x - gemm_blocks) * blockDim.x + threadIdx.x;
        int stride = (gridDim.x - gemm_blocks) * blockDim.x;
        for (int e = base; e < E; e += stride) {
            int col = ei[E + e];
            if ((unsigned)col < (unsigned)N) atomicAdd(&g_ideg[col], 1);
        }
        return;
    }

    // ---- gemm blocks ----
    extern __shared__ uint2 s_w2[];
    uint2* s_wh = s_w2;              // 4096 uint2
    uint2* s_wl = s_w2 + 4096;       // 4096 uint2

    {   // stage 64KB of W fragments
        uint4* dh = (uint4*)s_wh;
        uint4* dl = (uint4*)s_wl;
        const uint4* sh = (const uint4*)g_wfh2;
        const uint4* sl = (const uint4*)g_wfl2;
#pragma unroll
        for (int i = threadIdx.x; i < 2048; i += 256) {
            dh[i] = sh[i];
            dl[i] = sl[i];
        }
    }
    __syncthreads();

    int warp = (blockIdx.x * blockDim.x + threadIdx.x) >> 5;
    int lane = threadIdx.x & 31;
    int g = lane >> 2;
    int tig = lane & 3;
    int m0 = warp * 16;
    if (m0 >= N) return;

    int r0i = m0 + g;       if (r0i > N - 1) r0i = N - 1;
    int r1i = m0 + g + 8;   if (r1i > N - 1) r1i = N - 1;

    float d[16][4];
#pragma unroll
    for (int nt = 0; nt < 16; nt++)
#pragma unroll
        for (int c = 0; c < 4; c++) d[nt][c] = 0.f;

    const float2* x2 = (const float2*)x;
    long long rowA = (long long)r0i * 64;
    long long rowA8 = (long long)r1i * 64;

#pragma unroll
    for (int kt = 0; kt < 8; kt++) {
        int kb = kt * 8 + tig;
        uint32_t ah0, ah1, ah2, ah3, al0, al1, al2, al3;
        split2(x2[rowA + kb], ah0, al0);
        split2(x2[rowA8 + kb], ah1, al1);
        split2(x2[rowA + kb + 4], ah2, al2);
        split2(x2[rowA8 + kb + 4], ah3, al3);
#pragma unroll
        for (int nt = 0; nt < 16; nt++) {
            int p = (kt * 16 + nt) * 32 + lane;
            uint2 bh = s_wh[p];
            uint2 bl = s_wl[p];
            mma16816(d[nt], ah0, ah1, ah2, ah3, bh.x, bh.y);
            mma16816(d[nt], ah0, ah1, ah2, ah3, bl.x, bl.y);
            mma16816(d[nt], al0, al1, al2, al3, bh.x, bh.y);
        }
    }

    float* h = (float*)g_h;
    int r0 = m0 + g;
    int r1 = m0 + g + 8;
#pragma unroll
    for (int nt = 0; nt < 16; nt++) {
        int c = nt * 8 + tig * 2;
        if (r0 < N)
            *(float2*)&h[(long long)r0 * 128 + c] = make_float2(d[nt][0], d[nt][1]);
        if (r1 < N)
            *(float2*)&h[(long long)r1 * 128 + c] = make_float2(d[nt][2], d[nt][3]);
    }
}

// -------- 4a. per-block degree sums --------
__global__ void scan_blocksum_kernel(int N) {
    __shared__ int s[SCAN_BLK];
    int i = blockIdx.x * SCAN_BLK + threadIdx.x;
    s[threadIdx.x] = (i < N) ? g_ideg[i] : 0;
    __syncthreads();
    for (int off = SCAN_BLK / 2; off > 0; off >>= 1) {
        if (threadIdx.x < off) s[threadIdx.x] += s[threadIdx.x + off];
        __syncthreads();
    }
    if (threadIdx.x == 0) g_bsum[blockIdx.x] = s[0];
}

// -------- 4b. scan_final: offset via reduce of g_bsum[0..blockIdx) --
__global__ void scan_final_kernel(int N) {
    __shared__ int s[SCAN_BLK];
    __shared__ int red[SCAN_BLK];
    __shared__ int s_off;
    int t = threadIdx.x;

    int part = 0;
    for (int j = t; j < blockIdx.x; j += SCAN_BLK) part += g_bsum[j];
    red[t] = part;
    __syncthreads();
    for (int off = SCAN_BLK / 2; off > 0; off >>= 1) {
        if (t < off) red[t] += red[t + off];
        __syncthreads();
    }
    if (t == 0) s_off = red[0];
    __syncthreads();

    int i = blockIdx.x * SCAN_BLK + t;
    int v = (i < N) ? g_ideg[i] : 0;
    s[t] = v;
    __syncthreads();
    for (int off = 1; off < SCAN_BLK; off <<= 1) {
        int add = (t >= off) ? s[t - off] : 0;
        __syncthreads();
        s[t] += add;
        __syncthreads();
    }
    if (i < N) {
        int start = s_off + s[t] - v;
        g_indptr[i] = start;
        g_cursor[i] = start;
        g_dinv[i] = rsqrtf((float)(v + 1));
    }
}

// -------- 5. CSR fill --------
__global__ void fill_kernel(const int* __restrict__ ei, int E, int N) {
    int e = blockIdx.x * blockDim.x + threadIdx.x;
    if (e < E) {
        int row = ei[e];
        int col = ei[E + e];
        if ((unsigned)row < (unsigned)N && (unsigned)col < (unsigned)N) {
            int pos = atomicAdd(&g_cursor[col], 1);
            if ((unsigned)pos < (unsigned)EMAX) g_srcs[pos] = row;
        }
    }
}

// -------- 6. gather + fused BN stats --------
#define GATHER_BLOCKS 1184
__global__ void __launch_bounds__(256) gather_kernel(
        const float* __restrict__ b, int N) {
    __shared__ float s_sum[DFEAT];
    __shared__ float s_sumsq[DFEAT];
    int tid = threadIdx.x;
    if (tid < DFEAT) { s_sum[tid] = 0.f; s_sumsq[tid] = 0.f; }
    __syncthreads();

    int lane = tid & 31;
    int warp_g = (blockIdx.x * blockDim.x + tid) >> 5;
    int nwarps = (GATHER_BLOCKS * 256) >> 5;

    float4 bb = ((const float4*)b)[lane];

    float ps0 = 0.f, ps1 = 0.f, ps2 = 0.f, ps3 = 0.f;
    float q0 = 0.f, q1 = 0.f, q2 = 0.f, q3 = 0.f;

    for (int w = warp_g; w < N; w += nwarps) {
        float di = g_dinv[w];
        int start = g_indptr[w];
        int cnt = g_ideg[w];

        float4 a = __ldg(&g_h[w * 32 + lane]);
        float selfn = di * di;
        a.x = fmaf(a.x, selfn, bb.x);
        a.y = fmaf(a.y, selfn, bb.y);
        a.z = fmaf(a.z, selfn, bb.z);
        a.w = fmaf(a.w, selfn, bb.w);

        for (int base = 0; base < cnt; base += 32) {
            int j = base + lane;
            int src = 0;
            float nm = 0.f;
            if (j < cnt) {
                src = g_srcs[start + j];
                nm = di * g_dinv[src];
            }
            int m = cnt - base; if (m > 32) m = 32;

            int t = 0;
            for (; t + 4 <= m; t += 4) {
                int r0 = __shfl_sync(0xffffffffu, src, t + 0);
                int r1 = __shfl_sync(0xffffffffu, src, t + 1);
                int r2 = __shfl_sync(0xffffffffu, src, t + 2);
                int r3 = __shfl_sync(0xffffffffu, src, t + 3);
                float n0 = __shfl_sync(0xffffffffu, nm, t + 0);
                float n1 = __shfl_sync(0xffffffffu, nm, t + 1);
                float n2 = __shfl_sync(0xffffffffu, nm, t + 2);
                float n3 = __shfl_sync(0xffffffffu, nm, t + 3);
                float4 v0 = __ldg(&g_h[r0 * 32 + lane]);
                float4 v1 = __ldg(&g_h[r1 * 32 + lane]);
                float4 v2 = __ldg(&g_h[r2 * 32 + lane]);
                float4 v3 = __ldg(&g_h[r3 * 32 + lane]);
                a.x = fmaf(v0.x, n0, a.x); a.y = fmaf(v0.y, n0, a.y);
                a.z = fmaf(v0.z, n0, a.z); a.w = fmaf(v0.w, n0, a.w);
                a.x = fmaf(v1.x, n1, a.x); a.y = fmaf(v1.y, n1, a.y);
                a.z = fmaf(v1.z, n1, a.z); a.w = fmaf(v1.w, n1, a.w);
                a.x = fmaf(v2.x, n2, a.x); a.y = fmaf(v2.y, n2, a.y);
                a.z = fmaf(v2.z, n2, a.z); a.w = fmaf(v2.w, n2, a.w);
                a.x = fmaf(v3.x, n3, a.x); a.y = fmaf(v3.y, n3, a.y);
                a.z = fmaf(v3.z, n3, a.z); a.w = fmaf(v3.w, n3, a.w);
            }
            for (; t < m; t++) {
                int r = __shfl_sync(0xffffffffu, src, t);
                float nn = __shfl_sync(0xffffffffu, nm, t);
                float4 v = __ldg(&g_h[r * 32 + lane]);
                a.x = fmaf(v.x, nn, a.x); a.y = fmaf(v.y, nn, a.y);
                a.z = fmaf(v.z, nn, a.z); a.w = fmaf(v.w, nn, a.w);
            }
        }

        g_acc[w * 32 + lane] = a;

        ps0 += a.x; ps1 += a.y; ps2 += a.z; ps3 += a.w;
        q0 = fmaf(a.x, a.x, q0); q1 = fmaf(a.y, a.y, q1);
        q2 = fmaf(a.z, a.z, q2); q3 = fmaf(a.w, a.w, q3);
    }

    int c = lane * 4;
    atomicAdd(&s_sum[c + 0], ps0);
    atomicAdd(&s_sum[c + 1], ps1);
    atomicAdd(&s_sum[c + 2], ps2);
    atomicAdd(&s_sum[c + 3], ps3);
    atomicAdd(&s_sumsq[c + 0], q0);
    atomicAdd(&s_sumsq[c + 1], q1);
    atomicAdd(&s_sumsq[c + 2], q2);
    atomicAdd(&s_sumsq[c + 3], q3);
    __syncthreads();

    if (tid < DFEAT) {
        atomicAdd(&g_sum[tid], s_sum[tid]);
        atomicAdd(&g_sumsq[tid], s_sumsq[tid]);
    }
}

// -------- 7. BN normalize + relu + residual --------
__global__ void finalize_kernel(const float* __restrict__ x,
                                const float* __restrict__ gamma,
                                const float* __restrict__ beta,
                                float* __restrict__ out, int N) {
    int i = blockIdx.x * blockDim.x + threadIdx.x;
    int total = N * 32;
    if (i >= total) return;
    int d4 = i & 31;
    float inv_n = 1.0f / (float)N;

    float4 a  = g_acc[i];
    float4 xv = ((const float4*)x)[i];
    float4 g  = ((const float4*)gamma)[d4];
    float4 bt = ((const float4*)beta)[d4];
    float4 sm = ((const float4*)g_sum)[d4];
    float4 sq = ((const float4*)g_sumsq)[d4];

    float4 o;
    {
        float m = sm.x * inv_n;
        float var = sq.x * inv_n - m * m;
        float v = (a.x - m) * rsqrtf(var + BN_EPS) * g.x + bt.x;
        o.x = fmaxf(v, 0.f) + xv.x;
    }
    {
        float m = sm.y * inv_n;
        float var = sq.y * inv_n - m * m;
        float v = (a.y - m) * rsqrtf(var + BN_EPS) * g.y + bt.y;
        o.y = fmaxf(v, 0.f) + xv.y;
    }
    {
        float m = sm.z * inv_n;
        float var = sq.z * inv_n - m * m;
        float v = (a.z - m) * rsqrtf(var + BN_EPS) * g.z + bt.z;
        o.z = fmaxf(v, 0.f) + xv.z;
    }
    {
        float m = sm.w * inv_n;
        float var = sq.w * inv_n - m * m;
        float v = (a.w - m) * rsqrtf(var + BN_EPS) * g.w + bt.w;
        o.w = fmaxf(v, 0.f) + xv.w;
    }
    ((float4*)out)[i] = o;
}

extern "C" void kernel_launch(void* const* d_in, const int* in_sizes, int n_in,
                              void* d_out, int out_size) {
    const float* x     = (const float*)d_in[0];
    const int*   ei    = (const int*)d_in[1];
    const float* W     = (const float*)d_in[2];
    const float* b     = (const float*)d_in[3];
    const float* gamma = (const float*)d_in[4];
    const float* beta  = (const float*)d_in[5];
    float*       out   = (float*)d_out;

    int N = in_sizes[0] / DFEAT;
    int E = in_sizes[1] / 2;
    if (E > EMAX) E = EMAX;
    int NB = (N + SCAN_BLK - 1) / SCAN_BLK;   // 196 (<= 256)

    int nstrips = (N + 15) / 16;
    int gemm_blocks = (nstrips + 7) / 8;   // 391
    int deg_blocks = 512;                  // appended; hidden in gemm tail
    const int GEMM_SMEM = 65536;

    cudaFuncSetAttribute(gemm_degree_kernel,
                         cudaFuncAttributeMaxDynamicSharedMemorySize, GEMM_SMEM);

    init_kernel<<<(N + 255) / 256, 256>>>(N);                            // 1
    pack_w_kernel<<<16, 256>>>(W);                                       // 2
    gemm_degree_kernel<<<gemm_blocks + deg_blocks, 256, GEMM_SMEM>>>(
        x, ei, E, N, gemm_blocks);                                       // 3
    scan_blocksum_kernel<<<NB, SCAN_BLK>>>(N);                           // 4
    scan_final_kernel<<<NB, SCAN_BLK>>>(N);                              // 5
    fill_kernel<<<(E + 255) / 256, 256>>>(ei, E, N);                     // 6
    gather_kernel<<<GATHER_BLOCKS, 256>>>(b, N);                         // 7
    finalize_kernel<<<(N * 32 + 255) / 256, 256>>>(x, gamma, beta, out, N); // 8
}